// round 7
// baseline (speedup 1.0000x reference)
#include <cuda_runtime.h>
#include <cuda_fp16.h>
#include <math.h>
#include <stdint.h>

#define XLEN 2048
#define YLEN 1024
#define BSZ  8
#define XD   1024
#define YD   1024
#define HD   512
#define YOUT 1024
#define CATD (YD + HD)
#define FMAXV 3.402823466e38f
#define INV_SQRT_HD 0.04419417382415922f

// ===================== PTX helpers =====================
__device__ __forceinline__ uint32_t smem_u32(const void* p) {
    uint32_t a;
    asm("{ .reg .u64 t; cvta.to.shared.u64 t, %1; cvt.u32.u64 %0, t; }" : "=r"(a) : "l"(p));
    return a;
}
#define CP16(dst, src) \
    asm volatile("cp.async.cg.shared.global [%0], [%1], 16;" :: "r"(dst), "l"(src))
#define CP_COMMIT() asm volatile("cp.async.commit_group;")

#define LDSM4(r, a) \
    asm volatile("ldmatrix.sync.aligned.m8n8.x4.shared.b16 {%0,%1,%2,%3}, [%4];" \
        : "=r"((r)[0]), "=r"((r)[1]), "=r"((r)[2]), "=r"((r)[3]) : "r"(a))

#define MMA_F16(d, a, b0v, b1v) \
    asm volatile("mma.sync.aligned.m16n8k16.row.col.f32.f16.f16.f32 " \
        "{%0,%1,%2,%3}, {%4,%5,%6,%7}, {%8,%9}, {%0,%1,%2,%3};" \
        : "+f"((d)[0]), "+f"((d)[1]), "+f"((d)[2]), "+f"((d)[3]) \
        : "r"((a)[0]), "r"((a)[1]), "r"((a)[2]), "r"((a)[3]), "r"(b0v), "r"(b1v))

// SMEM tile: rows x 32 f16 (64B/row, 4 x 16B chunks), bank-conflict swizzle.
__device__ __forceinline__ uint32_t swz(int row, int chunk) {
    return (uint32_t)(row * 64 + ((chunk ^ ((row >> 1) & 3)) << 4));
}

// ===================== scratch (device globals) ==========================
#define AL __align__(16)
__device__ AL __half g_Xhi[XLEN * BSZ * XD];
__device__ AL __half g_cat_hi[YLEN * BSZ * CATD];
__device__ AL __half g_Xkw_hi[HD * XD],  g_Xkw_lo[HD * XD];
__device__ AL __half g_Xvw_hi[HD * XD];
__device__ AL __half g_Yqw_hi[HD * YD],  g_Yqw_lo[HD * YD];
__device__ AL __half g_Yww_hi[YOUT * CATD];
__device__ AL __half g_xk_hi[XLEN * BSZ * HD], g_xk_lo[XLEN * BSZ * HD];
__device__ AL __half g_xv_hi[XLEN * BSZ * HD];
__device__ AL __half g_yq_hi[YLEN * BSZ * HD];
__device__ AL __half g_xvT_hi[BSZ * HD * XLEN];
__device__ AL float  g_logits[BSZ * YLEN * XLEN];
__device__ AL __half g_attn_hi[BSZ * YLEN * XLEN];

// ===================== fused split: fp32 -> fp16 (hi [, lo]) =============
struct SplitArgs {
    const float* src[6];
    __half* hi[6];
    __half* lo[6];       // null -> hi only
    int incols[6], outld[6];
    long n4[6];
};

__global__ __launch_bounds__(256) void split_all(SplitArgs s)
{
    const int e = blockIdx.y;
    long i4 = (long)blockIdx.x * 256 + threadIdx.x;
    if (i4 >= s.n4[e]) return;
    long base = i4 * 4;
    long r = base / s.incols[e], c = base - r * s.incols[e];
    float4 v = *(const float4*)(s.src[e] + base);
    __half h0 = __float2half_rn(v.x), h1 = __float2half_rn(v.y),
           h2 = __float2half_rn(v.z), h3 = __float2half_rn(v.w);
    long off = r * s.outld[e] + c;
    __half2 hp0 = {h0, h1}, hp1 = {h2, h3};
    *(uint2*)(s.hi[e] + off) = make_uint2(*(uint32_t*)&hp0, *(uint32_t*)&hp1);
    if (s.lo[e]) {
        __half l0 = __float2half_rn(v.x - __half2float(h0));
        __half l1 = __float2half_rn(v.y - __half2float(h1));
        __half l2 = __float2half_rn(v.z - __half2float(h2));
        __half l3 = __float2half_rn(v.w - __half2float(h3));
        __half2 lp0 = {l0, l1}, lp1 = {l2, l3};
        *(uint2*)(s.lo[e] + off) = make_uint2(*(uint32_t*)&lp0, *(uint32_t*)&lp1);
    }
}

// ===================== transpose xv (x*b,h) -> (b,h,x) ===================
__global__ __launch_bounds__(256) void transpose_xv()
{
    __shared__ __half th[32][33];
    int b = blockIdx.z;
    int x0 = blockIdx.x * 32, h0 = blockIdx.y * 32;
    int tx = threadIdx.x, ty = threadIdx.y;
#pragma unroll
    for (int i = ty; i < 32; i += 8) {
        long src = ((long)(x0 + i) * BSZ + b) * HD + h0 + tx;
        th[i][tx] = g_xv_hi[src];
    }
    __syncthreads();
#pragma unroll
    for (int i = ty; i < 32; i += 8) {
        long dst = (long)b * HD * XLEN + (long)(h0 + i) * XLEN + x0 + tx;
        g_xvT_hi[dst] = th[tx][i];
    }
}

// ===================== softmax: fp32 logits -> fp16 attn =================
__global__ __launch_bounds__(256) void softmax_kernel()
{
    const long row = blockIdx.x;
    const float* p = g_logits + row * XLEN;
    __half* ah = g_attn_hi + row * XLEN;
    const int tid = threadIdx.x;

    float v[8];
    float mx = -FMAXV;
#pragma unroll
    for (int i = 0; i < 8; i++) { v[i] = p[tid + (i << 8)]; mx = fmaxf(mx, v[i]); }

    __shared__ float sred[8];
#pragma unroll
    for (int o = 16; o > 0; o >>= 1) mx = fmaxf(mx, __shfl_xor_sync(0xffffffff, mx, o));
    if ((tid & 31) == 0) sred[tid >> 5] = mx;
    __syncthreads();
    mx = sred[0];
#pragma unroll
    for (int w = 1; w < 8; w++) mx = fmaxf(mx, sred[w]);
    __syncthreads();

    float s = 0.0f;
#pragma unroll
    for (int i = 0; i < 8; i++) { v[i] = expf(v[i] - mx); s += v[i]; }
#pragma unroll
    for (int o = 16; o > 0; o >>= 1) s += __shfl_xor_sync(0xffffffff, s, o);
    if ((tid & 31) == 0) sred[tid >> 5] = s;
    __syncthreads();
    s = 0.0f;
#pragma unroll
    for (int w = 0; w < 8; w++) s += sred[w];

    const float inv = 1.0f / s;
#pragma unroll
    for (int i = 0; i < 8; i++)
        ah[tid + (i << 8)] = __float2half_rn(v[i] * inv);
}

// ===================== fp16 GEMM (1 or 2 B-terms) ========================
// C[M,N] = Ah[M,K] @ (Bh [+Bl])[N,K]^T
// Block 256x128, BK=32, 8 warps (4x2), warp tile 64x64, 4-stage cp.async,
// 1 CTA/SM. Single sync per iter.
struct GemmArgs {
    const __half *Ah, *Bh, *Bl;
    long lda, ldb, Abatch, Bbatch;
    int K;
    float* Cf;
    __half *Chi, *Clo;
    long ldc, Cbatch;
    const float* bias;
    float scale;
    const float* align;
    const int*   mask;
    const float* alignw;
};

template <int MODE, int TERMS>
__global__ __launch_bounds__(256, 1) void mma_gemm(GemmArgs g)
{
    constexpr int STG  = (TERMS == 2) ? 32768 : 24576;  // A 16K | Bh 8K | [Bl 8K]
    constexpr int NSTG = 4;
    constexpr int OFF_B  = 16384;
    constexpr int OFF_BL = 24576;

    extern __shared__ char smem[];
    const uint32_t sb = smem_u32(smem);
    const int tid = threadIdx.x, wid = tid >> 5, lane = tid & 31;
    const int b = blockIdx.z;
    const long m0 = (long)blockIdx.y * 256, n0 = (long)blockIdx.x * 128;
    const int wm = (wid >> 1) * 64;
    const int wn = (wid & 1) * 64;

    const __half* Ah = g.Ah + (long)b * g.Abatch;
    const __half* Bh = g.Bh + (long)b * g.Bbatch;
    const __half* Bl = g.Bl ? g.Bl + (long)b * g.Bbatch : (const __half*)0;

    // A: 256 rows x 4 chunks = 1024 chunks -> 4 per thread
    uint32_t aswz[4]; long gaof[4];
#pragma unroll
    for (int i = 0; i < 4; i++) {
        int cid = tid + i * 256;
        int row = cid >> 2, ch = cid & 3;
        aswz[i] = swz(row, ch);
        gaof[i] = (m0 + row) * g.lda + ch * 8;
    }
    // B: 128 rows x 4 chunks = 512 chunks -> 2 per thread
    uint32_t bswz[2]; long gbof[2];
#pragma unroll
    for (int i = 0; i < 2; i++) {
        int cid = tid + i * 256;
        int row = cid >> 2, ch = cid & 3;
        bswz[i] = swz(row, ch);
        gbof[i] = (n0 + row) * g.ldb + ch * 8;
    }

    const int NT = g.K >> 5;

    const int a_r = (lane & 15), a_c = (lane >> 4);
    const int b_r = (lane & 7) + ((lane >> 4) & 1) * 8, b_c = (lane >> 3) & 1;

    float acc[4][8][4];
#pragma unroll
    for (int i = 0; i < 4; i++)
#pragma unroll
        for (int j = 0; j < 8; j++)
#pragma unroll
            for (int k = 0; k < 4; k++) acc[i][j][k] = 0.0f;

    auto load_stage = [&](int s, int it) {
        const long k0 = (long)it << 5;
        const uint32_t base = sb + s * STG;
#pragma unroll
        for (int i = 0; i < 4; i++)
            CP16(base + aswz[i], (const char*)(Ah + gaof[i] + k0));
#pragma unroll
        for (int i = 0; i < 2; i++) {
            CP16(base + OFF_B + bswz[i], (const char*)(Bh + gbof[i] + k0));
            if (TERMS == 2)
                CP16(base + OFF_BL + bswz[i], (const char*)(Bl + gbof[i] + k0));
        }
        CP_COMMIT();
    };

#pragma unroll
    for (int p = 0; p < NSTG - 1; p++) load_stage(p, p);

    int cur = 0, nxt = NSTG - 1;
    for (int it = 0; it < NT; ++it) {
        asm volatile("cp.async.wait_group %0;" :: "n"(NSTG - 2));
        __syncthreads();
        // prefetch into the stage consumed at iter it-1 (sync above proves done)
        if (it + NSTG - 1 < NT) {
            load_stage(nxt, it + NSTG - 1);
            if (++nxt == NSTG) nxt = 0;
        } else CP_COMMIT();

        const uint32_t st = sb + cur * STG;
        if (++cur == NSTG) cur = 0;
#pragma unroll
        for (int ks = 0; ks < 2; ks++) {
            const int kc = ks * 2;
            uint32_t ah[4][4], bh[4][4], bl[4][4];
#pragma unroll
            for (int mi = 0; mi < 4; mi++)
                LDSM4(ah[mi], st + swz(wm + mi * 16 + a_r, kc + a_c));
#pragma unroll
            for (int nb = 0; nb < 4; nb++) {
                const uint32_t bo = swz(wn + nb * 16 + b_r, kc + b_c);
                LDSM4(bh[nb], st + OFF_B + bo);
                if (TERMS == 2) LDSM4(bl[nb], st + OFF_BL + bo);
            }
#pragma unroll
            for (int mi = 0; mi < 4; mi++)
#pragma unroll
                for (int ni = 0; ni < 8; ni++) {
                    const int nb = ni >> 1, sub = (ni & 1) * 2;
                    MMA_F16(acc[mi][ni], ah[mi], bh[nb][sub], bh[nb][sub + 1]);
                    if (TERMS == 2)
                        MMA_F16(acc[mi][ni], ah[mi], bl[nb][sub], bl[nb][sub + 1]);
                }
        }
    }
    __syncthreads();

    // ===================== epilogue =====================
    const float sig = (MODE == 1) ? (1.0f / (1.0f + expf(-__ldg(g.alignw)))) : 0.0f;

#pragma unroll
    for (int mi = 0; mi < 4; mi++) {
#pragma unroll
        for (int ni = 0; ni < 8; ni++) {
#pragma unroll
            for (int h = 0; h < 2; h++) {
                const long row = m0 + wm + mi * 16 + (lane >> 2) + h * 8;
                const long col = n0 + wn + ni * 8 + (lane & 3) * 2;
                float v0 = acc[mi][ni][h * 2 + 0];
                float v1 = acc[mi][ni][h * 2 + 1];
                const long idx = (long)b * g.Cbatch + row * g.ldc + col;
                if (MODE == 0) {
                    if (g.bias) { v0 += g.bias[col]; v1 += g.bias[col + 1]; }
                    v0 *= g.scale; v1 *= g.scale;
                    __half h0 = __float2half_rn(v0), h1 = __float2half_rn(v1);
                    __half2 hh = {h0, h1};
                    *(uint32_t*)(g.Chi + idx) = *(uint32_t*)&hh;
                    if (g.Clo) {
                        __half l0 = __float2half_rn(v0 - __half2float(h0));
                        __half l1 = __float2half_rn(v1 - __half2float(h1));
                        __half2 ll = {l0, l1};
                        *(uint32_t*)(g.Clo + idx) = *(uint32_t*)&ll;
                    }
                } else if (MODE == 1) {
                    float2 av = *(const float2*)(g.align + idx);
                    int2 mv = *(const int2*)(g.mask + idx);
                    float o0 = v0 + sig * av.x;
                    float o1 = v1 + sig * av.y;
                    o0 = fmaxf(o0, -FMAXV);
                    o1 = fmaxf(o1, -FMAXV);
                    if (mv.x != 0) o0 = fmaxf(o0 - FMAXV, -FMAXV);
                    if (mv.y != 0) o1 = fmaxf(o1 - FMAXV, -FMAXV);
                    *(float2*)(g.Cf + idx) = make_float2(o0, o1);
                } else {
                    v0 += g.bias[col];
                    v1 += g.bias[col + 1];
                    *(float2*)(g.Cf + idx) = make_float2(v0, v1);
                }
            }
        }
    }
}

// ===================== launch ============================================
extern "C" void kernel_launch(void* const* d_in, const int* in_sizes, int n_in,
                              void* d_out, int out_size)
{
    const float* X         = (const float*)d_in[0];
    const float* Y         = (const float*)d_in[1];
    const float* alignment = (const float*)d_in[2];
    const int*   mask      = (const int*)d_in[3];
    const float* Xk_w      = (const float*)d_in[4];
    const float* Xk_b      = (const float*)d_in[5];
    const float* Xv_w      = (const float*)d_in[6];
    const float* Xv_b      = (const float*)d_in[7];
    const float* Yq_w      = (const float*)d_in[8];
    const float* Yq_b      = (const float*)d_in[9];
    const float* Yw_w      = (const float*)d_in[10];
    const float* Yw_b      = (const float*)d_in[11];
    const float* align_w   = (const float*)d_in[12];
    float* out = (float*)d_out;

    const int SM2 = 4 * 32768;   // TERMS=2
    const int SM1 = 4 * 24576;   // TERMS=1
    cudaFuncSetAttribute((const void*)mma_gemm<0, 2>, cudaFuncAttributeMaxDynamicSharedMemorySize, SM2);
    cudaFuncSetAttribute((const void*)mma_gemm<1, 2>, cudaFuncAttributeMaxDynamicSharedMemorySize, SM2);
    cudaFuncSetAttribute((const void*)mma_gemm<0, 1>, cudaFuncAttributeMaxDynamicSharedMemorySize, SM1);
    cudaFuncSetAttribute((const void*)mma_gemm<2, 1>, cudaFuncAttributeMaxDynamicSharedMemorySize, SM1);

#define SYM(p, s) do { void* _t; cudaGetSymbolAddress(&_t, s); p = (decltype(p))_t; } while (0)
    __half *Xhi, *cat_hi, *Xkw_hi, *Xkw_lo, *Xvw_hi,
        *Yqw_hi, *Yqw_lo, *Yww_hi, *xk_hi, *xk_lo, *xv_hi,
        *yq_hi, *xvT_hi, *attn_hi;
    float* logits;
    SYM(Xhi, g_Xhi); SYM(cat_hi, g_cat_hi);
    SYM(Xkw_hi, g_Xkw_hi); SYM(Xkw_lo, g_Xkw_lo); SYM(Xvw_hi, g_Xvw_hi);
    SYM(Yqw_hi, g_Yqw_hi); SYM(Yqw_lo, g_Yqw_lo); SYM(Yww_hi, g_Yww_hi);
    SYM(xk_hi, g_xk_hi); SYM(xk_lo, g_xk_lo); SYM(xv_hi, g_xv_hi);
    SYM(yq_hi, g_yq_hi); SYM(xvT_hi, g_xvT_hi);
    SYM(attn_hi, g_attn_hi); SYM(logits, g_logits);

    // ---- fused split (1 launch) ----
    SplitArgs sa;
    sa.src[0] = X;    sa.hi[0] = Xhi;    sa.lo[0] = nullptr;
    sa.incols[0] = XD;   sa.outld[0] = XD;   sa.n4[0] = (long)XLEN * BSZ * XD / 4;
    sa.src[1] = Y;    sa.hi[1] = cat_hi; sa.lo[1] = nullptr;
    sa.incols[1] = YD;   sa.outld[1] = CATD; sa.n4[1] = (long)YLEN * BSZ * YD / 4;
    sa.src[2] = Xk_w; sa.hi[2] = Xkw_hi; sa.lo[2] = Xkw_lo;
    sa.incols[2] = XD;   sa.outld[2] = XD;   sa.n4[2] = (long)HD * XD / 4;
    sa.src[3] = Xv_w; sa.hi[3] = Xvw_hi; sa.lo[3] = nullptr;
    sa.incols[3] = XD;   sa.outld[3] = XD;   sa.n4[3] = (long)HD * XD / 4;
    sa.src[4] = Yq_w; sa.hi[4] = Yqw_hi; sa.lo[4] = Yqw_lo;
    sa.incols[4] = YD;   sa.outld[4] = YD;   sa.n4[4] = (long)HD * YD / 4;
    sa.src[5] = Yw_w; sa.hi[5] = Yww_hi; sa.lo[5] = nullptr;
    sa.incols[5] = CATD; sa.outld[5] = CATD; sa.n4[5] = (long)YOUT * CATD / 4;
    long maxn4 = sa.n4[0];
    for (int i = 1; i < 6; i++) if (sa.n4[i] > maxn4) maxn4 = sa.n4[i];
    split_all<<<dim3((unsigned)((maxn4 + 255) / 256), 6), 256>>>(sa);

    GemmArgs a = {};

    // ---- xk = X @ Xk_w^T + b : M=16384 N=512 K=1024 (2-term, hi+lo out) ----
    a.Ah = Xhi; a.lda = XD; a.Abatch = 0;
    a.Bh = Xkw_hi; a.Bl = Xkw_lo; a.ldb = XD; a.Bbatch = 0;
    a.K = XD; a.Chi = xk_hi; a.Clo = xk_lo; a.ldc = HD; a.Cbatch = 0;
    a.bias = Xk_b; a.scale = 1.0f;
    mma_gemm<0, 2><<<dim3(HD / 128, XLEN * BSZ / 256, 1), 256, SM2>>>(a);

    // ---- xv = X @ Xv_w^T + b (1-term, hi out) ----
    a.Bh = Xvw_hi; a.Bl = nullptr; a.Chi = xv_hi; a.Clo = nullptr; a.bias = Xv_b;
    mma_gemm<0, 1><<<dim3(HD / 128, XLEN * BSZ / 256, 1), 256, SM1>>>(a);

    // ---- yq = (Y @ Yq_w^T + b) / sqrt(HD) : M=8192 N=512 (2-term, hi out) ----
    a.Ah = cat_hi; a.lda = CATD;
    a.Bh = Yqw_hi; a.Bl = Yqw_lo; a.ldb = YD;
    a.Chi = yq_hi; a.Clo = nullptr; a.bias = Yq_b; a.scale = INV_SQRT_HD;
    mma_gemm<0, 2><<<dim3(HD / 128, YLEN * BSZ / 256, 1), 256, SM2>>>(a);

    // ---- transpose xv -> (b,h,x) ----
    transpose_xv<<<dim3(XLEN / 32, HD / 32, BSZ), dim3(32, 8)>>>();

    // ---- logits[b,y,x] : per batch M=1024 N=2048 K=512 (2-term) ----
    a = {};
    a.Ah = yq_hi; a.lda = BSZ * HD; a.Abatch = HD;
    a.Bh = xk_hi; a.Bl = xk_lo; a.ldb = BSZ * HD; a.Bbatch = HD;
    a.K = HD; a.Cf = logits; a.ldc = XLEN; a.Cbatch = (long)YLEN * XLEN;
    a.align = alignment; a.mask = mask; a.alignw = align_w; a.scale = 1.0f;
    mma_gemm<1, 2><<<dim3(XLEN / 128, YLEN / 256, BSZ), 256, SM2>>>(a);

    // ---- softmax -> attn (hi only) ----
    softmax_kernel<<<BSZ * YLEN, 256>>>();

    // ---- attn_feat = attn @ xvT^T -> cat[:, 1024:1536] (1-term) ----
    a = {};
    a.Ah = attn_hi; a.lda = XLEN; a.Abatch = (long)YLEN * XLEN;
    a.Bh = xvT_hi; a.Bl = nullptr; a.ldb = XLEN; a.Bbatch = (long)HD * XLEN;
    a.K = XLEN; a.Chi = cat_hi + YD; a.Clo = nullptr;
    a.ldc = (long)BSZ * CATD; a.Cbatch = CATD; a.bias = nullptr; a.scale = 1.0f;
    mma_gemm<0, 1><<<dim3(HD / 128, YLEN / 256, BSZ), 256, SM1>>>(a);

    // ---- out = cat @ Yw_w^T + b : M=8192 N=1024 K=1536 (1-term) ----
    a = {};
    a.Ah = cat_hi; a.lda = CATD; a.Abatch = 0;
    a.Bh = Yww_hi; a.Bl = nullptr; a.ldb = CATD; a.Bbatch = 0;
    a.K = CATD; a.Cf = out; a.ldc = YOUT; a.Cbatch = 0; a.bias = Yw_b; a.scale = 1.0f;
    mma_gemm<2, 1><<<dim3(YOUT / 128, YLEN * BSZ / 256, 1), 256, SM1>>>(a);
}

// round 8
// speedup vs baseline: 1.4168x; 1.4168x over previous
#include <cuda_runtime.h>
#include <cuda_fp16.h>
#include <math.h>
#include <stdint.h>

#define XLEN 2048
#define YLEN 1024
#define BSZ  8
#define XD   1024
#define YD   1024
#define HD   512
#define YOUT 1024
#define CATD (YD + HD)
#define FMAXV 3.402823466e38f
#define INV_SQRT_HD 0.04419417382415922f

// ===================== PTX helpers =====================
__device__ __forceinline__ uint32_t smem_u32(const void* p) {
    uint32_t a;
    asm("{ .reg .u64 t; cvta.to.shared.u64 t, %1; cvt.u32.u64 %0, t; }" : "=r"(a) : "l"(p));
    return a;
}
#define CP16(dst, src) \
    asm volatile("cp.async.cg.shared.global [%0], [%1], 16;" :: "r"(dst), "l"(src))
#define CP_COMMIT() asm volatile("cp.async.commit_group;")

#define LDSM4(r, a) \
    asm volatile("ldmatrix.sync.aligned.m8n8.x4.shared.b16 {%0,%1,%2,%3}, [%4];" \
        : "=r"((r)[0]), "=r"((r)[1]), "=r"((r)[2]), "=r"((r)[3]) : "r"(a))

#define MMA_F16(d, a, b0v, b1v) \
    asm volatile("mma.sync.aligned.m16n8k16.row.col.f32.f16.f16.f32 " \
        "{%0,%1,%2,%3}, {%4,%5,%6,%7}, {%8,%9}, {%0,%1,%2,%3};" \
        : "+f"((d)[0]), "+f"((d)[1]), "+f"((d)[2]), "+f"((d)[3]) \
        : "r"((a)[0]), "r"((a)[1]), "r"((a)[2]), "r"((a)[3]), "r"(b0v), "r"(b1v))

// SMEM tile: 128 rows x 32 f16 (64B/row, 4 x 16B chunks), bank-conflict swizzle.
__device__ __forceinline__ uint32_t swz(int row, int chunk) {
    return (uint32_t)(row * 64 + ((chunk ^ ((row >> 1) & 3)) << 4));
}

// ===================== scratch (device globals) ==========================
#define AL __align__(16)
__device__ AL __half g_Xhi[XLEN * BSZ * XD];
__device__ AL __half g_cat_hi[YLEN * BSZ * CATD];
__device__ AL __half g_Xkw_hi[HD * XD];
__device__ AL __half g_Xvw_hi[HD * XD];
__device__ AL __half g_Yqw_hi[HD * YD];
__device__ AL __half g_Yww_hi[YOUT * CATD];
__device__ AL __half g_xk_hi[XLEN * BSZ * HD];
__device__ AL __half g_xv_hi[XLEN * BSZ * HD];
__device__ AL __half g_yq_hi[YLEN * BSZ * HD];
__device__ AL __half g_xvT_hi[BSZ * HD * XLEN];
__device__ AL float  g_logits[BSZ * YLEN * XLEN];
__device__ AL __half g_attn_hi[BSZ * YLEN * XLEN];

// ===================== fused split: fp32 -> fp16 hi ======================
struct SplitArgs {
    const float* src[6];
    __half* hi[6];
    int incols[6], outld[6];
    long n4[6];
};

__global__ __launch_bounds__(256) void split_all(SplitArgs s)
{
    const int e = blockIdx.y;
    long i4 = (long)blockIdx.x * 256 + threadIdx.x;
    if (i4 >= s.n4[e]) return;
    long base = i4 * 4;
    long r = base / s.incols[e], c = base - r * s.incols[e];
    float4 v = *(const float4*)(s.src[e] + base);
    __half2 hp0 = {__float2half_rn(v.x), __float2half_rn(v.y)};
    __half2 hp1 = {__float2half_rn(v.z), __float2half_rn(v.w)};
    long off = r * s.outld[e] + c;
    *(uint2*)(s.hi[e] + off) = make_uint2(*(uint32_t*)&hp0, *(uint32_t*)&hp1);
}

// ===================== transpose xv (x*b,h) -> (b,h,x) ===================
__global__ __launch_bounds__(256) void transpose_xv()
{
    __shared__ __half th[32][33];
    int b = blockIdx.z;
    int x0 = blockIdx.x * 32, h0 = blockIdx.y * 32;
    int tx = threadIdx.x, ty = threadIdx.y;
#pragma unroll
    for (int i = ty; i < 32; i += 8) {
        long src = ((long)(x0 + i) * BSZ + b) * HD + h0 + tx;
        th[i][tx] = g_xv_hi[src];
    }
    __syncthreads();
#pragma unroll
    for (int i = ty; i < 32; i += 8) {
        long dst = (long)b * HD * XLEN + (long)(h0 + i) * XLEN + x0 + tx;
        g_xvT_hi[dst] = th[tx][i];
    }
}

// ===================== softmax: fp32 logits -> fp16 attn =================
__global__ __launch_bounds__(256) void softmax_kernel()
{
    const long row = blockIdx.x;
    const float* p = g_logits + row * XLEN;
    __half* ah = g_attn_hi + row * XLEN;
    const int tid = threadIdx.x;

    float v[8];
    float mx = -FMAXV;
#pragma unroll
    for (int i = 0; i < 8; i++) { v[i] = p[tid + (i << 8)]; mx = fmaxf(mx, v[i]); }

    __shared__ float sred[8];
#pragma unroll
    for (int o = 16; o > 0; o >>= 1) mx = fmaxf(mx, __shfl_xor_sync(0xffffffff, mx, o));
    if ((tid & 31) == 0) sred[tid >> 5] = mx;
    __syncthreads();
    mx = sred[0];
#pragma unroll
    for (int w = 1; w < 8; w++) mx = fmaxf(mx, sred[w]);
    __syncthreads();

    float s = 0.0f;
#pragma unroll
    for (int i = 0; i < 8; i++) { v[i] = expf(v[i] - mx); s += v[i]; }
#pragma unroll
    for (int o = 16; o > 0; o >>= 1) s += __shfl_xor_sync(0xffffffff, s, o);
    if ((tid & 31) == 0) sred[tid >> 5] = s;
    __syncthreads();
    s = 0.0f;
#pragma unroll
    for (int w = 0; w < 8; w++) s += sred[w];

    const float inv = 1.0f / s;
#pragma unroll
    for (int i = 0; i < 8; i++)
        ah[tid + (i << 8)] = __float2half_rn(v[i] * inv);
}

// ===================== fp16 GEMM (single term) ===========================
// C[M,N] = Ah[M,K] @ Bh[N,K]^T
// Block 128x128, BK=32, 8 warps (2x4), warp tile 64x32, 4-stage cp.async,
// 2 CTAs/SM (64KB smem each). Single sync per iter.
struct GemmArgs {
    const __half *Ah, *Bh;
    long lda, ldb, Abatch, Bbatch;
    int K;
    float* Cf;
    __half *Chi;
    long ldc, Cbatch;
    const float* bias;
    float scale;
    const float* align;
    const int*   mask;
    const float* alignw;
};

#define STG   16384            // Ah 8K | Bh 8K
#define NSTG  4
#define SMEM_BYTES (NSTG * STG)

template <int MODE>
__global__ __launch_bounds__(256, 2) void mma_gemm(GemmArgs g)
{
    extern __shared__ char smem[];
    const uint32_t sb = smem_u32(smem);
    const int tid = threadIdx.x, wid = tid >> 5, lane = tid & 31;
    const int b = blockIdx.z;
    const long m0 = (long)blockIdx.y * 128, n0 = (long)blockIdx.x * 128;
    const int wm = (wid >> 2) * 64;
    const int wn = (wid & 3) * 32;

    const __half* Ah = g.Ah + (long)b * g.Abatch;
    const __half* Bh = g.Bh + (long)b * g.Bbatch;

    const int r0c = tid >> 2,         ch0 = tid & 3;
    const int r1c = (tid + 256) >> 2, ch1 = (tid + 256) & 3;
    const uint32_t swA0 = swz(r0c, ch0), swA1 = swz(r1c, ch1);
    const long ga0 = (m0 + r0c) * g.lda + ch0 * 8;
    const long ga1 = (m0 + r1c) * g.lda + ch1 * 8;
    const long gb0 = (n0 + r0c) * g.ldb + ch0 * 8;
    const long gb1 = (n0 + r1c) * g.ldb + ch1 * 8;

    const int NT = g.K >> 5;

    const int a_r = (lane & 15), a_c = (lane >> 4);
    const int b_r = (lane & 7) + ((lane >> 4) & 1) * 8, b_c = (lane >> 3) & 1;

    float acc[4][4][4];
#pragma unroll
    for (int i = 0; i < 4; i++)
#pragma unroll
        for (int j = 0; j < 4; j++)
#pragma unroll
            for (int k = 0; k < 4; k++) acc[i][j][k] = 0.0f;

    auto load_stage = [&](int s, int it) {
        const long k0 = (long)it << 5;
        const uint32_t base = sb + s * STG;
        CP16(base + swA0,        (const char*)(Ah + ga0 + k0));
        CP16(base + swA1,        (const char*)(Ah + ga1 + k0));
        CP16(base + 8192 + swA0, (const char*)(Bh + gb0 + k0));
        CP16(base + 8192 + swA1, (const char*)(Bh + gb1 + k0));
        CP_COMMIT();
    };

#pragma unroll
    for (int p = 0; p < NSTG - 1; p++) load_stage(p, p);

    int cur = 0, nxt = NSTG - 1;
    for (int it = 0; it < NT; ++it) {
        asm volatile("cp.async.wait_group %0;" :: "n"(NSTG - 2));
        __syncthreads();
        // prefetch into the stage consumed at iter it-1 (sync above proves done)
        if (it + NSTG - 1 < NT) {
            load_stage(nxt, it + NSTG - 1);
            if (++nxt == NSTG) nxt = 0;
        } else CP_COMMIT();

        const uint32_t st = sb + cur * STG;
        if (++cur == NSTG) cur = 0;
#pragma unroll
        for (int ks = 0; ks < 2; ks++) {
            const int kc = ks * 2;
            uint32_t ah[4][4], bh[2][4];
#pragma unroll
            for (int mi = 0; mi < 4; mi++)
                LDSM4(ah[mi], st + swz(wm + mi * 16 + a_r, kc + a_c));
#pragma unroll
            for (int nb = 0; nb < 2; nb++)
                LDSM4(bh[nb], st + 8192 + swz(wn + nb * 16 + b_r, kc + b_c));
#pragma unroll
            for (int mi = 0; mi < 4; mi++)
#pragma unroll
                for (int ni = 0; ni < 4; ni++) {
                    const int nb = ni >> 1, sub = (ni & 1) * 2;
                    MMA_F16(acc[mi][ni], ah[mi], bh[nb][sub], bh[nb][sub + 1]);
                }
        }
    }
    __syncthreads();

    // ===================== epilogue =====================
    const float sig = (MODE == 1) ? (1.0f / (1.0f + expf(-__ldg(g.alignw)))) : 0.0f;

#pragma unroll
    for (int mi = 0; mi < 4; mi++) {
#pragma unroll
        for (int ni = 0; ni < 4; ni++) {
#pragma unroll
            for (int h = 0; h < 2; h++) {
                const long row = m0 + wm + mi * 16 + (lane >> 2) + h * 8;
                const long col = n0 + wn + ni * 8 + (lane & 3) * 2;
                float v0 = acc[mi][ni][h * 2 + 0];
                float v1 = acc[mi][ni][h * 2 + 1];
                const long idx = (long)b * g.Cbatch + row * g.ldc + col;
                if (MODE == 0) {
                    if (g.bias) { v0 += g.bias[col]; v1 += g.bias[col + 1]; }
                    v0 *= g.scale; v1 *= g.scale;
                    __half2 hh = {__float2half_rn(v0), __float2half_rn(v1)};
                    *(uint32_t*)(g.Chi + idx) = *(uint32_t*)&hh;
                } else if (MODE == 1) {
                    float2 av = *(const float2*)(g.align + idx);
                    int2 mv = *(const int2*)(g.mask + idx);
                    float o0 = v0 + sig * av.x;
                    float o1 = v1 + sig * av.y;
                    o0 = fmaxf(o0, -FMAXV);
                    o1 = fmaxf(o1, -FMAXV);
                    if (mv.x != 0) o0 = fmaxf(o0 - FMAXV, -FMAXV);
                    if (mv.y != 0) o1 = fmaxf(o1 - FMAXV, -FMAXV);
                    *(float2*)(g.Cf + idx) = make_float2(o0, o1);
                } else {
                    v0 += g.bias[col];
                    v1 += g.bias[col + 1];
                    *(float2*)(g.Cf + idx) = make_float2(v0, v1);
                }
            }
        }
    }
}

// ===================== launch ============================================
extern "C" void kernel_launch(void* const* d_in, const int* in_sizes, int n_in,
                              void* d_out, int out_size)
{
    const float* X         = (const float*)d_in[0];
    const float* Y         = (const float*)d_in[1];
    const float* alignment = (const float*)d_in[2];
    const int*   mask      = (const int*)d_in[3];
    const float* Xk_w      = (const float*)d_in[4];
    const float* Xk_b      = (const float*)d_in[5];
    const float* Xv_w      = (const float*)d_in[6];
    const float* Xv_b      = (const float*)d_in[7];
    const float* Yq_w      = (const float*)d_in[8];
    const float* Yq_b      = (const float*)d_in[9];
    const float* Yw_w      = (const float*)d_in[10];
    const float* Yw_b      = (const float*)d_in[11];
    const float* align_w   = (const float*)d_in[12];
    float* out = (float*)d_out;

    cudaFuncSetAttribute((const void*)mma_gemm<0>, cudaFuncAttributeMaxDynamicSharedMemorySize, SMEM_BYTES);
    cudaFuncSetAttribute((const void*)mma_gemm<1>, cudaFuncAttributeMaxDynamicSharedMemorySize, SMEM_BYTES);
    cudaFuncSetAttribute((const void*)mma_gemm<2>, cudaFuncAttributeMaxDynamicSharedMemorySize, SMEM_BYTES);

#define SYM(p, s) do { void* _t; cudaGetSymbolAddress(&_t, s); p = (decltype(p))_t; } while (0)
    __half *Xhi, *cat_hi, *Xkw_hi, *Xvw_hi, *Yqw_hi, *Yww_hi,
        *xk_hi, *xv_hi, *yq_hi, *xvT_hi, *attn_hi;
    float* logits;
    SYM(Xhi, g_Xhi); SYM(cat_hi, g_cat_hi);
    SYM(Xkw_hi, g_Xkw_hi); SYM(Xvw_hi, g_Xvw_hi);
    SYM(Yqw_hi, g_Yqw_hi); SYM(Yww_hi, g_Yww_hi);
    SYM(xk_hi, g_xk_hi); SYM(xv_hi, g_xv_hi);
    SYM(yq_hi, g_yq_hi); SYM(xvT_hi, g_xvT_hi);
    SYM(attn_hi, g_attn_hi); SYM(logits, g_logits);

    // ---- fused split (1 launch, all hi-only) ----
    SplitArgs sa;
    sa.src[0] = X;    sa.hi[0] = Xhi;
    sa.incols[0] = XD;   sa.outld[0] = XD;   sa.n4[0] = (long)XLEN * BSZ * XD / 4;
    sa.src[1] = Y;    sa.hi[1] = cat_hi;
    sa.incols[1] = YD;   sa.outld[1] = CATD; sa.n4[1] = (long)YLEN * BSZ * YD / 4;
    sa.src[2] = Xk_w; sa.hi[2] = Xkw_hi;
    sa.incols[2] = XD;   sa.outld[2] = XD;   sa.n4[2] = (long)HD * XD / 4;
    sa.src[3] = Xv_w; sa.hi[3] = Xvw_hi;
    sa.incols[3] = XD;   sa.outld[3] = XD;   sa.n4[3] = (long)HD * XD / 4;
    sa.src[4] = Yq_w; sa.hi[4] = Yqw_hi;
    sa.incols[4] = YD;   sa.outld[4] = YD;   sa.n4[4] = (long)HD * YD / 4;
    sa.src[5] = Yw_w; sa.hi[5] = Yww_hi;
    sa.incols[5] = CATD; sa.outld[5] = CATD; sa.n4[5] = (long)YOUT * CATD / 4;
    long maxn4 = sa.n4[0];
    for (int i = 1; i < 6; i++) if (sa.n4[i] > maxn4) maxn4 = sa.n4[i];
    split_all<<<dim3((unsigned)((maxn4 + 255) / 256), 6), 256>>>(sa);

    GemmArgs a = {};

    // ---- xk = X @ Xk_w^T + b : M=16384 N=512 K=1024 ----
    a.Ah = Xhi; a.lda = XD; a.Abatch = 0;
    a.Bh = Xkw_hi; a.ldb = XD; a.Bbatch = 0;
    a.K = XD; a.Chi = xk_hi; a.ldc = HD; a.Cbatch = 0;
    a.bias = Xk_b; a.scale = 1.0f;
    mma_gemm<0><<<dim3(HD / 128, XLEN * BSZ / 128, 1), 256, SMEM_BYTES>>>(a);

    // ---- xv = X @ Xv_w^T + b ----
    a.Bh = Xvw_hi; a.Chi = xv_hi; a.bias = Xv_b;
    mma_gemm<0><<<dim3(HD / 128, XLEN * BSZ / 128, 1), 256, SMEM_BYTES>>>(a);

    // ---- yq = (Y @ Yq_w^T + b) / sqrt(HD) : M=8192 N=512 K=1024 ----
    a.Ah = cat_hi; a.lda = CATD;
    a.Bh = Yqw_hi; a.ldb = YD;
    a.Chi = yq_hi; a.bias = Yq_b; a.scale = INV_SQRT_HD;
    mma_gemm<0><<<dim3(HD / 128, YLEN * BSZ / 128, 1), 256, SMEM_BYTES>>>(a);

    // ---- transpose xv -> (b,h,x) ----
    transpose_xv<<<dim3(XLEN / 32, HD / 32, BSZ), dim3(32, 8)>>>();

    // ---- logits[b,y,x] : per batch M=1024 N=2048 K=512 ----
    a = {};
    a.Ah = yq_hi; a.lda = BSZ * HD; a.Abatch = HD;
    a.Bh = xk_hi; a.ldb = BSZ * HD; a.Bbatch = HD;
    a.K = HD; a.Cf = logits; a.ldc = XLEN; a.Cbatch = (long)YLEN * XLEN;
    a.align = alignment; a.mask = mask; a.alignw = align_w; a.scale = 1.0f;
    mma_gemm<1><<<dim3(XLEN / 128, YLEN / 128, BSZ), 256, SMEM_BYTES>>>(a);

    // ---- softmax -> attn ----
    softmax_kernel<<<BSZ * YLEN, 256>>>();

    // ---- attn_feat = attn @ xvT^T -> cat[:, 1024:1536] ----
    a = {};
    a.Ah = attn_hi; a.lda = XLEN; a.Abatch = (long)YLEN * XLEN;
    a.Bh = xvT_hi; a.ldb = XLEN; a.Bbatch = (long)HD * XLEN;
    a.K = XLEN; a.Chi = cat_hi + YD;
    a.ldc = (long)BSZ * CATD; a.Cbatch = CATD; a.bias = nullptr; a.scale = 1.0f;
    mma_gemm<0><<<dim3(HD / 128, YLEN / 128, BSZ), 256, SMEM_BYTES>>>(a);

    // ---- out = cat @ Yw_w^T + b : M=8192 N=1024 K=1536 ----
    a = {};
    a.Ah = cat_hi; a.lda = CATD; a.Abatch = 0;
    a.Bh = Yww_hi; a.ldb = CATD; a.Bbatch = 0;
    a.K = CATD; a.Cf = out; a.ldc = YOUT; a.Cbatch = 0; a.bias = Yw_b; a.scale = 1.0f;
    mma_gemm<2><<<dim3(YOUT / 128, YLEN * BSZ / 128, 1), 256, SMEM_BYTES>>>(a);
}

// round 9
// speedup vs baseline: 1.6093x; 1.1359x over previous
#include <cuda_runtime.h>
#include <cuda_fp16.h>
#include <math.h>
#include <stdint.h>

#define XLEN 2048
#define YLEN 1024
#define BSZ  8
#define XD   1024
#define YD   1024
#define HD   512
#define YOUT 1024
#define CATD (YD + HD)
#define FMAXV 3.402823466e38f
#define INV_SQRT_HD 0.04419417382415922f

// ===================== PTX helpers =====================
__device__ __forceinline__ uint32_t smem_u32(const void* p) {
    uint32_t a;
    asm("{ .reg .u64 t; cvta.to.shared.u64 t, %1; cvt.u32.u64 %0, t; }" : "=r"(a) : "l"(p));
    return a;
}
#define CP16(dst, src) \
    asm volatile("cp.async.cg.shared.global [%0], [%1], 16;" :: "r"(dst), "l"(src))
#define CP_COMMIT() asm volatile("cp.async.commit_group;")

#define LDSM4(r, a) \
    asm volatile("ldmatrix.sync.aligned.m8n8.x4.shared.b16 {%0,%1,%2,%3}, [%4];" \
        : "=r"((r)[0]), "=r"((r)[1]), "=r"((r)[2]), "=r"((r)[3]) : "r"(a))

#define MMA_F16(d, a, b0v, b1v) \
    asm volatile("mma.sync.aligned.m16n8k16.row.col.f32.f16.f16.f32 " \
        "{%0,%1,%2,%3}, {%4,%5,%6,%7}, {%8,%9}, {%0,%1,%2,%3};" \
        : "+f"((d)[0]), "+f"((d)[1]), "+f"((d)[2]), "+f"((d)[3]) \
        : "r"((a)[0]), "r"((a)[1]), "r"((a)[2]), "r"((a)[3]), "r"(b0v), "r"(b1v))

// SMEM tile: 128 rows x 64 f16 (128B/row, 8 x 16B chunks).
// Swizzle: chunk ^= row&7 -> conflict-free for ldmatrix phases & stores.
__device__ __forceinline__ uint32_t swz64(int row, int ch) {
    return (uint32_t)(row * 128 + ((ch ^ (row & 7)) << 4));
}

// ===================== scratch (device globals) ==========================
#define AL __align__(16)
__device__ AL __half g_Xhi[XLEN * BSZ * XD];
__device__ AL __half g_cat_hi[YLEN * BSZ * CATD];
__device__ AL __half g_Xkw_hi[HD * XD];
__device__ AL __half g_Xvw_hi[HD * XD];
__device__ AL __half g_Yqw_hi[HD * YD];
__device__ AL __half g_Yww_hi[YOUT * CATD];
__device__ AL __half g_xk_hi[XLEN * BSZ * HD];
__device__ AL __half g_xv_hi[XLEN * BSZ * HD];
__device__ AL __half g_yq_hi[YLEN * BSZ * HD];
__device__ AL __half g_xvT_hi[BSZ * HD * XLEN];
__device__ AL float  g_logits[BSZ * YLEN * XLEN];
__device__ AL __half g_attn_hi[BSZ * YLEN * XLEN];

// ===================== fused split: fp32 -> fp16 hi ======================
struct SplitArgs {
    const float* src[6];
    __half* hi[6];
    int incols[6], outld[6];
    long n4[6];
};

__global__ __launch_bounds__(256) void split_all(SplitArgs s)
{
    const int e = blockIdx.y;
    long i4 = (long)blockIdx.x * 256 + threadIdx.x;
    if (i4 >= s.n4[e]) return;
    long base = i4 * 4;
    long r = base / s.incols[e], c = base - r * s.incols[e];
    float4 v = *(const float4*)(s.src[e] + base);
    __half2 hp0 = {__float2half_rn(v.x), __float2half_rn(v.y)};
    __half2 hp1 = {__float2half_rn(v.z), __float2half_rn(v.w)};
    long off = r * s.outld[e] + c;
    *(uint2*)(s.hi[e] + off) = make_uint2(*(uint32_t*)&hp0, *(uint32_t*)&hp1);
}

// ===================== transpose xv (x*b,h) -> (b,h,x) ===================
__global__ __launch_bounds__(256) void transpose_xv()
{
    __shared__ __half th[32][33];
    int b = blockIdx.z;
    int x0 = blockIdx.x * 32, h0 = blockIdx.y * 32;
    int tx = threadIdx.x, ty = threadIdx.y;
#pragma unroll
    for (int i = ty; i < 32; i += 8) {
        long src = ((long)(x0 + i) * BSZ + b) * HD + h0 + tx;
        th[i][tx] = g_xv_hi[src];
    }
    __syncthreads();
#pragma unroll
    for (int i = ty; i < 32; i += 8) {
        long dst = (long)b * HD * XLEN + (long)(h0 + i) * XLEN + x0 + tx;
        g_xvT_hi[dst] = th[tx][i];
    }
}

// ===================== softmax: fp32 logits -> fp16 attn =================
__global__ __launch_bounds__(256) void softmax_kernel()
{
    const long row = blockIdx.x;
    const float* p = g_logits + row * XLEN;
    __half* ah = g_attn_hi + row * XLEN;
    const int tid = threadIdx.x;

    float v[8];
    float mx = -FMAXV;
#pragma unroll
    for (int i = 0; i < 8; i++) { v[i] = p[tid + (i << 8)]; mx = fmaxf(mx, v[i]); }

    __shared__ float sred[8];
#pragma unroll
    for (int o = 16; o > 0; o >>= 1) mx = fmaxf(mx, __shfl_xor_sync(0xffffffff, mx, o));
    if ((tid & 31) == 0) sred[tid >> 5] = mx;
    __syncthreads();
    mx = sred[0];
#pragma unroll
    for (int w = 1; w < 8; w++) mx = fmaxf(mx, sred[w]);
    __syncthreads();

    float s = 0.0f;
#pragma unroll
    for (int i = 0; i < 8; i++) { v[i] = expf(v[i] - mx); s += v[i]; }
#pragma unroll
    for (int o = 16; o > 0; o >>= 1) s += __shfl_xor_sync(0xffffffff, s, o);
    if ((tid & 31) == 0) sred[tid >> 5] = s;
    __syncthreads();
    s = 0.0f;
#pragma unroll
    for (int w = 0; w < 8; w++) s += sred[w];

    const float inv = 1.0f / s;
#pragma unroll
    for (int i = 0; i < 8; i++)
        ah[tid + (i << 8)] = __float2half_rn(v[i] * inv);
}

// ===================== fp16 GEMM core ====================================
// C[M,N] = Ah[M,K] @ Bh[N,K]^T
// Block 128x128, BK=64, 8 warps (2x4), warp tile 64x32, 3-stage cp.async
// (32KB/stage), 2 CTAs/SM. One sync per 64-K iter.
struct GemmArgs {
    const __half *Ah, *Bh;
    long lda, ldb, Abatch, Bbatch;
    int K;
    float* Cf;
    __half *Chi;
    long ldc, Cbatch;
    const float* bias;
    float scale;
    const float* align;
    const int*   mask;
    const float* alignw;
};

#define STG   32768            // Ah 16K | Bh 16K
#define NSTG  3
#define SMEM_BYTES (NSTG * STG)

template <int MODE>
__device__ __forceinline__ void gemm_body(const GemmArgs& g, int b)
{
    extern __shared__ char smem[];
    const uint32_t sb = smem_u32(smem);
    const int tid = threadIdx.x, wid = tid >> 5, lane = tid & 31;
    const long m0 = (long)blockIdx.y * 128, n0 = (long)blockIdx.x * 128;
    const int wm = (wid >> 2) * 64;
    const int wn = (wid & 3) * 32;

    const __half* Ah = g.Ah + (long)b * g.Abatch;
    const __half* Bh = g.Bh + (long)b * g.Bbatch;

    // load plan: thread covers (row = tid>>3 + 32i, chunk = tid&7), i=0..3
    const int lrow = tid >> 3, lch = tid & 7;
    const uint32_t sw0 = swz64(lrow, lch);
    const long ga0 = (m0 + lrow) * g.lda + lch * 8;
    const long gb0 = (n0 + lrow) * g.ldb + lch * 8;
    const long astep = 32 * g.lda, bstep = 32 * g.ldb;

    const int NT = g.K >> 6;
    const int a_r = lane & 15, a_c = lane >> 4;
    const int b_r = (lane & 7) + ((lane >> 4) & 1) * 8, b_c = (lane >> 3) & 1;

    float acc[4][4][4];
#pragma unroll
    for (int i = 0; i < 4; i++)
#pragma unroll
        for (int j = 0; j < 4; j++)
#pragma unroll
            for (int k = 0; k < 4; k++) acc[i][j][k] = 0.0f;

    auto load_stage = [&](int s, int it) {
        const long k0 = (long)it << 6;
        const uint32_t base = sb + s * STG;
#pragma unroll
        for (int i = 0; i < 4; i++) {
            CP16(base + sw0 + i * 4096,         (const char*)(Ah + ga0 + i * astep + k0));
            CP16(base + 16384 + sw0 + i * 4096, (const char*)(Bh + gb0 + i * bstep + k0));
        }
        CP_COMMIT();
    };

    load_stage(0, 0);
    load_stage(1, 1);

    int cur = 0, nxt = 2;
    for (int it = 0; it < NT; ++it) {
        asm volatile("cp.async.wait_group 1;");
        __syncthreads();
        // prefetch into the stage consumed at iter it-1 (sync above proves done)
        if (it + 2 < NT) {
            load_stage(nxt, it + 2);
            if (++nxt == NSTG) nxt = 0;
        } else CP_COMMIT();

        const uint32_t st = sb + cur * STG;
        if (++cur == NSTG) cur = 0;
#pragma unroll
        for (int ks = 0; ks < 4; ks++) {
            const int kc = ks * 2;
            uint32_t ah[4][4], bh[2][4];
#pragma unroll
            for (int mi = 0; mi < 4; mi++)
                LDSM4(ah[mi], st + swz64(wm + mi * 16 + a_r, kc + a_c));
#pragma unroll
            for (int nb = 0; nb < 2; nb++)
                LDSM4(bh[nb], st + 16384 + swz64(wn + nb * 16 + b_r, kc + b_c));
#pragma unroll
            for (int mi = 0; mi < 4; mi++)
#pragma unroll
                for (int ni = 0; ni < 4; ni++) {
                    const int nb = ni >> 1, sub = (ni & 1) * 2;
                    MMA_F16(acc[mi][ni], ah[mi], bh[nb][sub], bh[nb][sub + 1]);
                }
        }
    }
    __syncthreads();

    // ===================== epilogue =====================
    const float sig = (MODE == 1) ? (1.0f / (1.0f + expf(-__ldg(g.alignw)))) : 0.0f;

#pragma unroll
    for (int mi = 0; mi < 4; mi++) {
#pragma unroll
        for (int ni = 0; ni < 4; ni++) {
#pragma unroll
            for (int h = 0; h < 2; h++) {
                const long row = m0 + wm + mi * 16 + (lane >> 2) + h * 8;
                const long col = n0 + wn + ni * 8 + (lane & 3) * 2;
                float v0 = acc[mi][ni][h * 2 + 0];
                float v1 = acc[mi][ni][h * 2 + 1];
                const long idx = (long)b * g.Cbatch + row * g.ldc + col;
                if (MODE == 0) {
                    if (g.bias) { v0 += g.bias[col]; v1 += g.bias[col + 1]; }
                    v0 *= g.scale; v1 *= g.scale;
                    __half2 hh = {__float2half_rn(v0), __float2half_rn(v1)};
                    *(uint32_t*)(g.Chi + idx) = *(uint32_t*)&hh;
                } else if (MODE == 1) {
                    float2 av = *(const float2*)(g.align + idx);
                    int2 mv = *(const int2*)(g.mask + idx);
                    float o0 = v0 + sig * av.x;
                    float o1 = v1 + sig * av.y;
                    o0 = fmaxf(o0, -FMAXV);
                    o1 = fmaxf(o1, -FMAXV);
                    if (mv.x != 0) o0 = fmaxf(o0 - FMAXV, -FMAXV);
                    if (mv.y != 0) o1 = fmaxf(o1 - FMAXV, -FMAXV);
                    *(float2*)(g.Cf + idx) = make_float2(o0, o1);
                } else {
                    v0 += g.bias[col];
                    v1 += g.bias[col + 1];
                    *(float2*)(g.Cf + idx) = make_float2(v0, v1);
                }
            }
        }
    }
}

template <int MODE>
__global__ __launch_bounds__(256, 2) void mma_gemm(GemmArgs g)
{
    gemm_body<MODE>(g, blockIdx.z);
}

// merged projections: z selects config; batch strides are 0 so b=0
struct Gemm3 { GemmArgs a[3]; long Mrows[3]; };
__global__ __launch_bounds__(256, 2) void mma_gemm_proj(Gemm3 p)
{
    const int z = blockIdx.z;
    if ((long)blockIdx.y * 128 >= p.Mrows[z]) return;
    gemm_body<0>(p.a[z], 0);
}

// ===================== launch ============================================
extern "C" void kernel_launch(void* const* d_in, const int* in_sizes, int n_in,
                              void* d_out, int out_size)
{
    const float* X         = (const float*)d_in[0];
    const float* Y         = (const float*)d_in[1];
    const float* alignment = (const float*)d_in[2];
    const int*   mask      = (const int*)d_in[3];
    const float* Xk_w      = (const float*)d_in[4];
    const float* Xk_b      = (const float*)d_in[5];
    const float* Xv_w      = (const float*)d_in[6];
    const float* Xv_b      = (const float*)d_in[7];
    const float* Yq_w      = (const float*)d_in[8];
    const float* Yq_b      = (const float*)d_in[9];
    const float* Yw_w      = (const float*)d_in[10];
    const float* Yw_b      = (const float*)d_in[11];
    const float* align_w   = (const float*)d_in[12];
    float* out = (float*)d_out;

    cudaFuncSetAttribute((const void*)mma_gemm<0>, cudaFuncAttributeMaxDynamicSharedMemorySize, SMEM_BYTES);
    cudaFuncSetAttribute((const void*)mma_gemm<1>, cudaFuncAttributeMaxDynamicSharedMemorySize, SMEM_BYTES);
    cudaFuncSetAttribute((const void*)mma_gemm<2>, cudaFuncAttributeMaxDynamicSharedMemorySize, SMEM_BYTES);
    cudaFuncSetAttribute((const void*)mma_gemm_proj, cudaFuncAttributeMaxDynamicSharedMemorySize, SMEM_BYTES);

#define SYM(p, s) do { void* _t; cudaGetSymbolAddress(&_t, s); p = (decltype(p))_t; } while (0)
    __half *Xhi, *cat_hi, *Xkw_hi, *Xvw_hi, *Yqw_hi, *Yww_hi,
        *xk_hi, *xv_hi, *yq_hi, *xvT_hi, *attn_hi;
    float* logits;
    SYM(Xhi, g_Xhi); SYM(cat_hi, g_cat_hi);
    SYM(Xkw_hi, g_Xkw_hi); SYM(Xvw_hi, g_Xvw_hi);
    SYM(Yqw_hi, g_Yqw_hi); SYM(Yww_hi, g_Yww_hi);
    SYM(xk_hi, g_xk_hi); SYM(xv_hi, g_xv_hi);
    SYM(yq_hi, g_yq_hi); SYM(xvT_hi, g_xvT_hi);
    SYM(attn_hi, g_attn_hi); SYM(logits, g_logits);

    // ---- fused split (1 launch, all hi-only) ----
    SplitArgs sa;
    sa.src[0] = X;    sa.hi[0] = Xhi;
    sa.incols[0] = XD;   sa.outld[0] = XD;   sa.n4[0] = (long)XLEN * BSZ * XD / 4;
    sa.src[1] = Y;    sa.hi[1] = cat_hi;
    sa.incols[1] = YD;   sa.outld[1] = CATD; sa.n4[1] = (long)YLEN * BSZ * YD / 4;
    sa.src[2] = Xk_w; sa.hi[2] = Xkw_hi;
    sa.incols[2] = XD;   sa.outld[2] = XD;   sa.n4[2] = (long)HD * XD / 4;
    sa.src[3] = Xv_w; sa.hi[3] = Xvw_hi;
    sa.incols[3] = XD;   sa.outld[3] = XD;   sa.n4[3] = (long)HD * XD / 4;
    sa.src[4] = Yq_w; sa.hi[4] = Yqw_hi;
    sa.incols[4] = YD;   sa.outld[4] = YD;   sa.n4[4] = (long)HD * YD / 4;
    sa.src[5] = Yw_w; sa.hi[5] = Yww_hi;
    sa.incols[5] = CATD; sa.outld[5] = CATD; sa.n4[5] = (long)YOUT * CATD / 4;
    long maxn4 = sa.n4[0];
    for (int i = 1; i < 6; i++) if (sa.n4[i] > maxn4) maxn4 = sa.n4[i];
    split_all<<<dim3((unsigned)((maxn4 + 255) / 256), 6), 256>>>(sa);

    // ---- merged projections: xk, xv, yq (one launch) ----
    Gemm3 p3 = {};
    {
        GemmArgs a = {};
        a.Ah = Xhi; a.lda = XD; a.Abatch = 0;
        a.Bh = Xkw_hi; a.ldb = XD; a.Bbatch = 0;
        a.K = XD; a.Chi = xk_hi; a.ldc = HD; a.Cbatch = 0;
        a.bias = Xk_b; a.scale = 1.0f;
        p3.a[0] = a; p3.Mrows[0] = (long)XLEN * BSZ;

        a.Bh = Xvw_hi; a.Chi = xv_hi; a.bias = Xv_b;
        p3.a[1] = a; p3.Mrows[1] = (long)XLEN * BSZ;

        a.Ah = cat_hi; a.lda = CATD;
        a.Bh = Yqw_hi; a.ldb = YD;
        a.Chi = yq_hi; a.bias = Yq_b; a.scale = INV_SQRT_HD;
        p3.a[2] = a; p3.Mrows[2] = (long)YLEN * BSZ;
    }
    mma_gemm_proj<<<dim3(HD / 128, XLEN * BSZ / 128, 3), 256, SMEM_BYTES>>>(p3);

    // ---- transpose xv -> (b,h,x) ----
    transpose_xv<<<dim3(XLEN / 32, HD / 32, BSZ), dim3(32, 8)>>>();

    GemmArgs a = {};

    // ---- logits[b,y,x] : per batch M=1024 N=2048 K=512 ----
    a.Ah = yq_hi; a.lda = BSZ * HD; a.Abatch = HD;
    a.Bh = xk_hi; a.ldb = BSZ * HD; a.Bbatch = HD;
    a.K = HD; a.Cf = logits; a.ldc = XLEN; a.Cbatch = (long)YLEN * XLEN;
    a.align = alignment; a.mask = mask; a.alignw = align_w; a.scale = 1.0f;
    mma_gemm<1><<<dim3(XLEN / 128, YLEN / 128, BSZ), 256, SMEM_BYTES>>>(a);

    // ---- softmax -> attn ----
    softmax_kernel<<<BSZ * YLEN, 256>>>();

    // ---- attn_feat = attn @ xvT^T -> cat[:, 1024:1536] ----
    a = {};
    a.Ah = attn_hi; a.lda = XLEN; a.Abatch = (long)YLEN * XLEN;
    a.Bh = xvT_hi; a.ldb = XLEN; a.Bbatch = (long)HD * XLEN;
    a.K = XLEN; a.Chi = cat_hi + YD;
    a.ldc = (long)BSZ * CATD; a.Cbatch = CATD; a.bias = nullptr; a.scale = 1.0f;
    mma_gemm<0><<<dim3(HD / 128, YLEN / 128, BSZ), 256, SMEM_BYTES>>>(a);

    // ---- out = cat @ Yw_w^T + b : M=8192 N=1024 K=1536 ----
    a = {};
    a.Ah = cat_hi; a.lda = CATD; a.Abatch = 0;
    a.Bh = Yww_hi; a.ldb = CATD; a.Bbatch = 0;
    a.K = CATD; a.Cf = out; a.ldc = YOUT; a.Cbatch = 0; a.bias = Yw_b; a.scale = 1.0f;
    mma_gemm<2><<<dim3(YOUT / 128, YLEN * BSZ / 128, 1), 256, SMEM_BYTES>>>(a);
}

// round 10
// speedup vs baseline: 1.6435x; 1.0212x over previous
#include <cuda_runtime.h>
#include <cuda_fp16.h>
#include <math.h>
#include <stdint.h>

#define XLEN 2048
#define YLEN 1024
#define BSZ  8
#define XD   1024
#define YD   1024
#define HD   512
#define YOUT 1024
#define CATD (YD + HD)
#define FMAXV 3.402823466e38f
#define INV_SQRT_HD 0.04419417382415922f

// ===================== PTX helpers =====================
__device__ __forceinline__ uint32_t smem_u32(const void* p) {
    uint32_t a;
    asm("{ .reg .u64 t; cvta.to.shared.u64 t, %1; cvt.u32.u64 %0, t; }" : "=r"(a) : "l"(p));
    return a;
}
#define CP16(dst, src) \
    asm volatile("cp.async.cg.shared.global [%0], [%1], 16;" :: "r"(dst), "l"(src))
#define CP_COMMIT() asm volatile("cp.async.commit_group;")

#define LDSM4(r, a) \
    asm volatile("ldmatrix.sync.aligned.m8n8.x4.shared.b16 {%0,%1,%2,%3}, [%4];" \
        : "=r"((r)[0]), "=r"((r)[1]), "=r"((r)[2]), "=r"((r)[3]) : "r"(a))

#define MMA_F16(d, a, b0v, b1v) \
    asm volatile("mma.sync.aligned.m16n8k16.row.col.f32.f16.f16.f32 " \
        "{%0,%1,%2,%3}, {%4,%5,%6,%7}, {%8,%9}, {%0,%1,%2,%3};" \
        : "+f"((d)[0]), "+f"((d)[1]), "+f"((d)[2]), "+f"((d)[3]) \
        : "r"((a)[0]), "r"((a)[1]), "r"((a)[2]), "r"((a)[3]), "r"(b0v), "r"(b1v))

// SMEM tile: 128 rows x 64 f16 (128B/row, 8 x 16B chunks).
// Swizzle: chunk ^= row&7 -> conflict-free for ldmatrix phases & stores.
__device__ __forceinline__ uint32_t swz64(int row, int ch) {
    return (uint32_t)(row * 128 + ((ch ^ (row & 7)) << 4));
}

// ===================== scratch (device globals) ==========================
#define AL __align__(16)
__device__ AL __half g_Xhi[XLEN * BSZ * XD];
__device__ AL __half g_cat_hi[YLEN * BSZ * CATD];
__device__ AL __half g_Xkw_hi[HD * XD];
__device__ AL __half g_Xvw_hi[HD * XD];
__device__ AL __half g_Yqw_hi[HD * YD];
__device__ AL __half g_Yww_hi[YOUT * CATD];
__device__ AL __half g_xk_hi[XLEN * BSZ * HD];
__device__ AL __half g_yq_hi[YLEN * BSZ * HD];
__device__ AL __half g_xvT_hi[BSZ * HD * XLEN];
__device__ AL float  g_logits[BSZ * YLEN * XLEN];
__device__ AL __half g_attn_hi[BSZ * YLEN * XLEN];

// ===================== fused split: fp32 -> fp16 hi ======================
struct SplitArgs {
    const float* src[6];
    __half* hi[6];
    int incols[6], outld[6];
    long n4[6];
};

__global__ __launch_bounds__(256) void split_all(SplitArgs s)
{
    const int e = blockIdx.y;
    long i4 = (long)blockIdx.x * 256 + threadIdx.x;
    if (i4 >= s.n4[e]) return;
    long base = i4 * 4;
    long r = base / s.incols[e], c = base - r * s.incols[e];
    float4 v = *(const float4*)(s.src[e] + base);
    __half2 hp0 = {__float2half_rn(v.x), __float2half_rn(v.y)};
    __half2 hp1 = {__float2half_rn(v.z), __float2half_rn(v.w)};
    long off = r * s.outld[e] + c;
    *(uint2*)(s.hi[e] + off) = make_uint2(*(uint32_t*)&hp0, *(uint32_t*)&hp1);
}

// ===================== softmax: fp32 logits -> fp16 attn =================
__global__ __launch_bounds__(256) void softmax_kernel()
{
    const long row = blockIdx.x;
    const float* p = g_logits + row * XLEN;
    __half* ah = g_attn_hi + row * XLEN;
    const int tid = threadIdx.x;

    float v[8];
    float mx = -FMAXV;
#pragma unroll
    for (int i = 0; i < 8; i++) { v[i] = p[tid + (i << 8)]; mx = fmaxf(mx, v[i]); }

    __shared__ float sred[8];
#pragma unroll
    for (int o = 16; o > 0; o >>= 1) mx = fmaxf(mx, __shfl_xor_sync(0xffffffff, mx, o));
    if ((tid & 31) == 0) sred[tid >> 5] = mx;
    __syncthreads();
    mx = sred[0];
#pragma unroll
    for (int w = 1; w < 8; w++) mx = fmaxf(mx, sred[w]);
    __syncthreads();

    float s = 0.0f;
#pragma unroll
    for (int i = 0; i < 8; i++) { v[i] = expf(v[i] - mx); s += v[i]; }
#pragma unroll
    for (int o = 16; o > 0; o >>= 1) s += __shfl_xor_sync(0xffffffff, s, o);
    if ((tid & 31) == 0) sred[tid >> 5] = s;
    __syncthreads();
    s = 0.0f;
#pragma unroll
    for (int w = 0; w < 8; w++) s += sred[w];

    const float inv = 1.0f / s;
#pragma unroll
    for (int i = 0; i < 8; i++)
        ah[tid + (i << 8)] = __float2half_rn(v[i] * inv);
}

// ===================== fp16 GEMM core ====================================
// C[M,N] = Ah[M,K] @ Bh[N,K]^T
// Block 128x128, BK=64, 8 warps (2x4), warp tile 64x32, 3-stage cp.async
// (32KB/stage), 2 CTAs/SM. One sync per 64-K iter.
// Epilogue: stage fp32 acc tile in (now idle) pipeline smem, then a
// thread-linear pass with fully coalesced 16B gmem accesses.
// MODE 0: fp16 out, optional bias (col or row), scale.
// MODE 1: logits: +sig*align, clamp, mask -> fp32.
// MODE 2: +bias -> fp32.
struct GemmArgs {
    const __half *Ah, *Bh;
    long lda, ldb, Abatch, Bbatch;
    int K;
    float* Cf;
    __half *Chi;
    long ldc, Cbatch;
    const float* bias;
    int bias_rows;          // 1: bias indexed by output row (xvT proj)
    float scale;
    const float* align;
    const int*   mask;
    const float* alignw;
};

#define STG   32768            // Ah 16K | Bh 16K
#define NSTG  3
#define EPIT  136              // staging pitch (floats): conflict-free
#define SMEM_BYTES (NSTG * STG)   // 96KB >= 128*136*4 = 69.6KB staging

template <int MODE>
__device__ __forceinline__ void gemm_body(const GemmArgs& g, int b)
{
    extern __shared__ char smem[];
    const uint32_t sb = smem_u32(smem);
    const int tid = threadIdx.x, wid = tid >> 5, lane = tid & 31;
    const long m0 = (long)blockIdx.y * 128, n0 = (long)blockIdx.x * 128;
    const int wm = (wid >> 2) * 64;
    const int wn = (wid & 3) * 32;

    const __half* Ah = g.Ah + (long)b * g.Abatch;
    const __half* Bh = g.Bh + (long)b * g.Bbatch;

    // load plan: thread covers (row = tid>>3 + 32i, chunk = tid&7), i=0..3
    const int lrow = tid >> 3, lch = tid & 7;
    const uint32_t sw0 = swz64(lrow, lch);
    const long ga0 = (m0 + lrow) * g.lda + lch * 8;
    const long gb0 = (n0 + lrow) * g.ldb + lch * 8;
    const long astep = 32 * g.lda, bstep = 32 * g.ldb;

    const int NT = g.K >> 6;
    const int a_r = lane & 15, a_c = lane >> 4;
    const int b_r = (lane & 7) + ((lane >> 4) & 1) * 8, b_c = (lane >> 3) & 1;

    float acc[4][4][4];
#pragma unroll
    for (int i = 0; i < 4; i++)
#pragma unroll
        for (int j = 0; j < 4; j++)
#pragma unroll
            for (int k = 0; k < 4; k++) acc[i][j][k] = 0.0f;

    auto load_stage = [&](int s, int it) {
        const long k0 = (long)it << 6;
        const uint32_t base = sb + s * STG;
#pragma unroll
        for (int i = 0; i < 4; i++) {
            CP16(base + sw0 + i * 4096,         (const char*)(Ah + ga0 + i * astep + k0));
            CP16(base + 16384 + sw0 + i * 4096, (const char*)(Bh + gb0 + i * bstep + k0));
        }
        CP_COMMIT();
    };

    load_stage(0, 0);
    load_stage(1, 1);

    int cur = 0, nxt = 2;
    for (int it = 0; it < NT; ++it) {
        asm volatile("cp.async.wait_group 1;");
        __syncthreads();
        if (it + 2 < NT) {
            load_stage(nxt, it + 2);
            if (++nxt == NSTG) nxt = 0;
        } else CP_COMMIT();

        const uint32_t st = sb + cur * STG;
        if (++cur == NSTG) cur = 0;
#pragma unroll
        for (int ks = 0; ks < 4; ks++) {
            const int kc = ks * 2;
            uint32_t ah[4][4], bh[2][4];
#pragma unroll
            for (int mi = 0; mi < 4; mi++)
                LDSM4(ah[mi], st + swz64(wm + mi * 16 + a_r, kc + a_c));
#pragma unroll
            for (int nb = 0; nb < 2; nb++)
                LDSM4(bh[nb], st + 16384 + swz64(wn + nb * 16 + b_r, kc + b_c));
#pragma unroll
            for (int mi = 0; mi < 4; mi++)
#pragma unroll
                for (int ni = 0; ni < 4; ni++) {
                    const int nb = ni >> 1, sub = (ni & 1) * 2;
                    MMA_F16(acc[mi][ni], ah[mi], bh[nb][sub], bh[nb][sub + 1]);
                }
        }
    }
    __syncthreads();   // pipeline smem now reusable as staging

    // ---- stage acc tile to smem (pitch 136 floats, conflict-free) ----
    float* sf = (float*)smem;
#pragma unroll
    for (int mi = 0; mi < 4; mi++)
#pragma unroll
        for (int ni = 0; ni < 4; ni++) {
            const int row = wm + mi * 16 + (lane >> 2);
            const int col = wn + ni * 8 + (lane & 3) * 2;
            *(float2*)&sf[row * EPIT + col] =
                make_float2(acc[mi][ni][0], acc[mi][ni][1]);
            *(float2*)&sf[(row + 8) * EPIT + col] =
                make_float2(acc[mi][ni][2], acc[mi][ni][3]);
        }
    __syncthreads();

    // ---- thread-linear gmem phase: coalesced 16B transactions ----
    if (MODE == 0) {
        const float sc = g.scale;
#pragma unroll
        for (int i = 0; i < 8; i++) {
            const int gid = tid + i * 256;
            const int row = gid >> 4, c0 = (gid & 15) * 8;
            float4 va = *(float4*)&sf[row * EPIT + c0];
            float4 vb = *(float4*)&sf[row * EPIT + c0 + 4];
            float v[8] = {va.x, va.y, va.z, va.w, vb.x, vb.y, vb.z, vb.w};
            if (g.bias) {
                if (g.bias_rows) {
                    const float br = __ldg(&g.bias[m0 + row]);
#pragma unroll
                    for (int j = 0; j < 8; j++) v[j] += br;
                } else {
                    float4 b0 = *(const float4*)&g.bias[n0 + c0];
                    float4 b1 = *(const float4*)&g.bias[n0 + c0 + 4];
                    v[0] += b0.x; v[1] += b0.y; v[2] += b0.z; v[3] += b0.w;
                    v[4] += b1.x; v[5] += b1.y; v[6] += b1.z; v[7] += b1.w;
                }
            }
            uint4 u;
            __half2 h0 = {__float2half_rn(v[0] * sc), __float2half_rn(v[1] * sc)};
            __half2 h1 = {__float2half_rn(v[2] * sc), __float2half_rn(v[3] * sc)};
            __half2 h2 = {__float2half_rn(v[4] * sc), __float2half_rn(v[5] * sc)};
            __half2 h3 = {__float2half_rn(v[6] * sc), __float2half_rn(v[7] * sc)};
            u.x = *(uint32_t*)&h0; u.y = *(uint32_t*)&h1;
            u.z = *(uint32_t*)&h2; u.w = *(uint32_t*)&h3;
            const long idx = (long)b * g.Cbatch + (m0 + row) * g.ldc + n0 + c0;
            *(uint4*)(g.Chi + idx) = u;
        }
    } else if (MODE == 1) {
        const float sig = 1.0f / (1.0f + expf(-__ldg(g.alignw)));
#pragma unroll
        for (int i = 0; i < 16; i++) {
            const int gid = tid + i * 256;
            const int row = gid >> 5, c0 = (gid & 31) * 4;
            float4 v = *(float4*)&sf[row * EPIT + c0];
            const long idx = (long)b * g.Cbatch + (m0 + row) * g.ldc + n0 + c0;
            float4 av = *(const float4*)(g.align + idx);
            int4   mv = *(const int4*)(g.mask + idx);
            float o0 = fmaxf(v.x + sig * av.x, -FMAXV);
            float o1 = fmaxf(v.y + sig * av.y, -FMAXV);
            float o2 = fmaxf(v.z + sig * av.z, -FMAXV);
            float o3 = fmaxf(v.w + sig * av.w, -FMAXV);
            if (mv.x != 0) o0 = fmaxf(o0 - FMAXV, -FMAXV);
            if (mv.y != 0) o1 = fmaxf(o1 - FMAXV, -FMAXV);
            if (mv.z != 0) o2 = fmaxf(o2 - FMAXV, -FMAXV);
            if (mv.w != 0) o3 = fmaxf(o3 - FMAXV, -FMAXV);
            *(float4*)(g.Cf + idx) = make_float4(o0, o1, o2, o3);
        }
    } else {
#pragma unroll
        for (int i = 0; i < 16; i++) {
            const int gid = tid + i * 256;
            const int row = gid >> 5, c0 = (gid & 31) * 4;
            float4 v = *(float4*)&sf[row * EPIT + c0];
            float4 b4 = *(const float4*)&g.bias[n0 + c0];
            const long idx = (long)b * g.Cbatch + (m0 + row) * g.ldc + n0 + c0;
            *(float4*)(g.Cf + idx) =
                make_float4(v.x + b4.x, v.y + b4.y, v.z + b4.z, v.w + b4.w);
        }
    }
}

template <int MODE>
__global__ __launch_bounds__(256, 2) void mma_gemm(GemmArgs g)
{
    gemm_body<MODE>(g, blockIdx.z);
}

// merged projections (xk, yq): z selects config; batch strides 0 so b=0
struct Gemm2 { GemmArgs a[2]; long Mrows[2]; };
__global__ __launch_bounds__(256, 2) void mma_gemm_proj(Gemm2 p)
{
    const int z = blockIdx.z;
    if ((long)blockIdx.y * 128 >= p.Mrows[z]) return;
    gemm_body<0>(p.a[z], 0);
}

// ===================== launch ============================================
extern "C" void kernel_launch(void* const* d_in, const int* in_sizes, int n_in,
                              void* d_out, int out_size)
{
    const float* X         = (const float*)d_in[0];
    const float* Y         = (const float*)d_in[1];
    const float* alignment = (const float*)d_in[2];
    const int*   mask      = (const int*)d_in[3];
    const float* Xk_w      = (const float*)d_in[4];
    const float* Xk_b      = (const float*)d_in[5];
    const float* Xv_w      = (const float*)d_in[6];
    const float* Xv_b      = (const float*)d_in[7];
    const float* Yq_w      = (const float*)d_in[8];
    const float* Yq_b      = (const float*)d_in[9];
    const float* Yw_w      = (const float*)d_in[10];
    const float* Yw_b      = (const float*)d_in[11];
    const float* align_w   = (const float*)d_in[12];
    float* out = (float*)d_out;

    cudaFuncSetAttribute((const void*)mma_gemm<0>, cudaFuncAttributeMaxDynamicSharedMemorySize, SMEM_BYTES);
    cudaFuncSetAttribute((const void*)mma_gemm<1>, cudaFuncAttributeMaxDynamicSharedMemorySize, SMEM_BYTES);
    cudaFuncSetAttribute((const void*)mma_gemm<2>, cudaFuncAttributeMaxDynamicSharedMemorySize, SMEM_BYTES);
    cudaFuncSetAttribute((const void*)mma_gemm_proj, cudaFuncAttributeMaxDynamicSharedMemorySize, SMEM_BYTES);

#define SYM(p, s) do { void* _t; cudaGetSymbolAddress(&_t, s); p = (decltype(p))_t; } while (0)
    __half *Xhi, *cat_hi, *Xkw_hi, *Xvw_hi, *Yqw_hi, *Yww_hi,
        *xk_hi, *yq_hi, *xvT_hi, *attn_hi;
    float* logits;
    SYM(Xhi, g_Xhi); SYM(cat_hi, g_cat_hi);
    SYM(Xkw_hi, g_Xkw_hi); SYM(Xvw_hi, g_Xvw_hi);
    SYM(Yqw_hi, g_Yqw_hi); SYM(Yww_hi, g_Yww_hi);
    SYM(xk_hi, g_xk_hi); SYM(yq_hi, g_yq_hi); SYM(xvT_hi, g_xvT_hi);
    SYM(attn_hi, g_attn_hi); SYM(logits, g_logits);

    // ---- fused split (1 launch, all hi-only) ----
    SplitArgs sa;
    sa.src[0] = X;    sa.hi[0] = Xhi;
    sa.incols[0] = XD;   sa.outld[0] = XD;   sa.n4[0] = (long)XLEN * BSZ * XD / 4;
    sa.src[1] = Y;    sa.hi[1] = cat_hi;
    sa.incols[1] = YD;   sa.outld[1] = CATD; sa.n4[1] = (long)YLEN * BSZ * YD / 4;
    sa.src[2] = Xk_w; sa.hi[2] = Xkw_hi;
    sa.incols[2] = XD;   sa.outld[2] = XD;   sa.n4[2] = (long)HD * XD / 4;
    sa.src[3] = Xv_w; sa.hi[3] = Xvw_hi;
    sa.incols[3] = XD;   sa.outld[3] = XD;   sa.n4[3] = (long)HD * XD / 4;
    sa.src[4] = Yq_w; sa.hi[4] = Yqw_hi;
    sa.incols[4] = YD;   sa.outld[4] = YD;   sa.n4[4] = (long)HD * YD / 4;
    sa.src[5] = Yw_w; sa.hi[5] = Yww_hi;
    sa.incols[5] = CATD; sa.outld[5] = CATD; sa.n4[5] = (long)YOUT * CATD / 4;
    long maxn4 = sa.n4[0];
    for (int i = 1; i < 6; i++) if (sa.n4[i] > maxn4) maxn4 = sa.n4[i];
    split_all<<<dim3((unsigned)((maxn4 + 255) / 256), 6), 256>>>(sa);

    // ---- merged projections: xk, yq (one launch) ----
    Gemm2 p2 = {};
    {
        GemmArgs a = {};
        a.Ah = Xhi; a.lda = XD; a.Abatch = 0;
        a.Bh = Xkw_hi; a.ldb = XD; a.Bbatch = 0;
        a.K = XD; a.Chi = xk_hi; a.ldc = HD; a.Cbatch = 0;
        a.bias = Xk_b; a.bias_rows = 0; a.scale = 1.0f;
        p2.a[0] = a; p2.Mrows[0] = (long)XLEN * BSZ;

        a.Ah = cat_hi; a.lda = CATD;
        a.Bh = Yqw_hi; a.ldb = YD;
        a.Chi = yq_hi; a.bias = Yq_b; a.scale = INV_SQRT_HD;
        p2.a[1] = a; p2.Mrows[1] = (long)YLEN * BSZ;
    }
    mma_gemm_proj<<<dim3(HD / 128, XLEN * BSZ / 128, 2), 256, SMEM_BYTES>>>(p2);

    GemmArgs a = {};

    // ---- xvT[b,h,x] = Xv_w @ X[.,b,.]^T + Xv_b (row bias) : per batch ----
    a.Ah = Xvw_hi; a.lda = XD; a.Abatch = 0;
    a.Bh = Xhi; a.ldb = (long)BSZ * XD; a.Bbatch = XD;
    a.K = XD; a.Chi = xvT_hi; a.ldc = XLEN; a.Cbatch = (long)HD * XLEN;
    a.bias = Xv_b; a.bias_rows = 1; a.scale = 1.0f;
    mma_gemm<0><<<dim3(XLEN / 128, HD / 128, BSZ), 256, SMEM_BYTES>>>(a);

    // ---- logits[b,y,x] : per batch M=1024 N=2048 K=512 ----
    a = {};
    a.Ah = yq_hi; a.lda = BSZ * HD; a.Abatch = HD;
    a.Bh = xk_hi; a.ldb = BSZ * HD; a.Bbatch = HD;
    a.K = HD; a.Cf = logits; a.ldc = XLEN; a.Cbatch = (long)YLEN * XLEN;
    a.align = alignment; a.mask = mask; a.alignw = align_w; a.scale = 1.0f;
    mma_gemm<1><<<dim3(XLEN / 128, YLEN / 128, BSZ), 256, SMEM_BYTES>>>(a);

    // ---- softmax -> attn ----
    softmax_kernel<<<BSZ * YLEN, 256>>>();

    // ---- attn_feat = attn @ xvT^T -> cat[:, 1024:1536] ----
    a = {};
    a.Ah = attn_hi; a.lda = XLEN; a.Abatch = (long)YLEN * XLEN;
    a.Bh = xvT_hi; a.ldb = XLEN; a.Bbatch = (long)HD * XLEN;
    a.K = XLEN; a.Chi = cat_hi + YD;
    a.ldc = (long)BSZ * CATD; a.Cbatch = CATD;
    a.bias = nullptr; a.bias_rows = 0; a.scale = 1.0f;
    mma_gemm<0><<<dim3(HD / 128, YLEN / 128, BSZ), 256, SMEM_BYTES>>>(a);

    // ---- out = cat @ Yw_w^T + b : M=8192 N=1024 K=1536 ----
    a = {};
    a.Ah = cat_hi; a.lda = CATD; a.Abatch = 0;
    a.Bh = Yww_hi; a.ldb = CATD; a.Bbatch = 0;
    a.K = CATD; a.Cf = out; a.ldc = YOUT; a.Cbatch = 0;
    a.bias = Yw_b; a.bias_rows = 0; a.scale = 1.0f;
    mma_gemm<2><<<dim3(YOUT / 128, YLEN * BSZ / 128, 1), 256, SMEM_BYTES>>>(a);
}

// round 11
// speedup vs baseline: 1.7224x; 1.0481x over previous
#include <cuda_runtime.h>
#include <cuda_fp16.h>
#include <math.h>
#include <stdint.h>

#define XLEN 2048
#define YLEN 1024
#define BSZ  8
#define XD   1024
#define YD   1024
#define HD   512
#define YOUT 1024
#define CATD (YD + HD)
#define FMAXV 3.402823466e38f
#define INV_SQRT_HD 0.04419417382415922f

// ===================== PTX helpers =====================
__device__ __forceinline__ uint32_t smem_u32(const void* p) {
    uint32_t a;
    asm("{ .reg .u64 t; cvta.to.shared.u64 t, %1; cvt.u32.u64 %0, t; }" : "=r"(a) : "l"(p));
    return a;
}
#define CP16(dst, src) \
    asm volatile("cp.async.cg.shared.global [%0], [%1], 16;" :: "r"(dst), "l"(src))
#define CP_COMMIT() asm volatile("cp.async.commit_group;")
#define PREF_L2(p) asm volatile("prefetch.global.L2 [%0];" :: "l"(p))

#define LDSM4(r, a) \
    asm volatile("ldmatrix.sync.aligned.m8n8.x4.shared.b16 {%0,%1,%2,%3}, [%4];" \
        : "=r"((r)[0]), "=r"((r)[1]), "=r"((r)[2]), "=r"((r)[3]) : "r"(a))

#define MMA_F16(d, a, b0v, b1v) \
    asm volatile("mma.sync.aligned.m16n8k16.row.col.f32.f16.f16.f32 " \
        "{%0,%1,%2,%3}, {%4,%5,%6,%7}, {%8,%9}, {%0,%1,%2,%3};" \
        : "+f"((d)[0]), "+f"((d)[1]), "+f"((d)[2]), "+f"((d)[3]) \
        : "r"((a)[0]), "r"((a)[1]), "r"((a)[2]), "r"((a)[3]), "r"(b0v), "r"(b1v))

// SMEM tile: 128 rows x 64 f16 (128B/row, 8 x 16B chunks), conflict-free swizzle.
__device__ __forceinline__ uint32_t swz64(int row, int ch) {
    return (uint32_t)(row * 128 + ((ch ^ (row & 7)) << 4));
}

// ===================== scratch (device globals) ==========================
#define AL __align__(16)
__device__ AL __half g_Xhi[XLEN * BSZ * XD];
__device__ AL __half g_Yhi[YLEN * BSZ * YD];
__device__ AL __half g_Xkw_hi[HD * XD];
__device__ AL __half g_Xvw_hi[HD * XD];
__device__ AL __half g_Yqw_hi[HD * YD];
__device__ AL __half g_Yww_hi[YOUT * CATD];
__device__ AL __half g_xk_hi[XLEN * BSZ * HD];
__device__ AL __half g_yq_hi[YLEN * BSZ * HD];
__device__ AL __half g_xvT_hi[BSZ * HD * XLEN];
__device__ AL __half g_af_hi[YLEN * BSZ * HD];
__device__ AL float  g_logits[BSZ * YLEN * XLEN];
__device__ AL __half g_attn_hi[BSZ * YLEN * XLEN];

// ===================== fused split: fp32 -> fp16 hi ======================
struct SplitArgs {
    const float* src[6];
    __half* hi[6];
    long n4[6];
};

__global__ __launch_bounds__(256) void split_all(SplitArgs s)
{
    const int e = blockIdx.y;
    long i4 = (long)blockIdx.x * 256 + threadIdx.x;
    if (i4 >= s.n4[e]) return;
    long base = i4 * 4;
    float4 v = *(const float4*)(s.src[e] + base);
    __half2 hp0 = {__float2half_rn(v.x), __float2half_rn(v.y)};
    __half2 hp1 = {__float2half_rn(v.z), __float2half_rn(v.w)};
    *(uint2*)(s.hi[e] + base) = make_uint2(*(uint32_t*)&hp0, *(uint32_t*)&hp1);
}

// ===================== softmax: fp32 logits -> fp16 attn =================
__global__ __launch_bounds__(256) void softmax_kernel()
{
    const long row = blockIdx.x;
    const float* p = g_logits + row * XLEN;
    __half* ah = g_attn_hi + row * XLEN;
    const int tid = threadIdx.x;

    float v[8];
    float mx = -FMAXV;
#pragma unroll
    for (int i = 0; i < 8; i++) { v[i] = p[tid + (i << 8)]; mx = fmaxf(mx, v[i]); }

    __shared__ float sred[8];
#pragma unroll
    for (int o = 16; o > 0; o >>= 1) mx = fmaxf(mx, __shfl_xor_sync(0xffffffff, mx, o));
    if ((tid & 31) == 0) sred[tid >> 5] = mx;
    __syncthreads();
    mx = sred[0];
#pragma unroll
    for (int w = 1; w < 8; w++) mx = fmaxf(mx, sred[w]);
    __syncthreads();

    float s = 0.0f;
#pragma unroll
    for (int i = 0; i < 8; i++) { v[i] = expf(v[i] - mx); s += v[i]; }
#pragma unroll
    for (int o = 16; o > 0; o >>= 1) s += __shfl_xor_sync(0xffffffff, s, o);
    if ((tid & 31) == 0) sred[tid >> 5] = s;
    __syncthreads();
    s = 0.0f;
#pragma unroll
    for (int w = 0; w < 8; w++) s += sred[w];

    const float inv = 1.0f / s;
#pragma unroll
    for (int i = 0; i < 8; i++)
        ah[tid + (i << 8)] = __float2half_rn(v[i] * inv);
}

// ===================== fp16 GEMM core ====================================
// C[M,N] = Ah[M,K] @ Bh[N,K]^T
// Block 128x128, BK=64, 8 warps (2x4), warp tile 64x32, 3-stage cp.async,
// 2 CTAs/SM. Smem-staged coalesced epilogues.
// MODE 0: fp16 out (+bias col/row, scale).  MODE 1: logits epilogue -> fp32.
// MODE 2: +bias -> fp32.  MODE 3: accumulate into fp32 C (no bias).
struct GemmArgs {
    const __half *Ah, *Bh;
    long lda, ldb, Abatch, Bbatch;
    int K;
    float* Cf;
    __half *Chi;
    long ldc, Cbatch;
    const float* bias;
    int bias_rows;
    float scale;
    const float* align;
    const int*   mask;
    const float* alignw;
};

#define STG   32768            // Ah 16K | Bh 16K
#define NSTG  3
#define EPIT  136
#define SMEM_BYTES (NSTG * STG)

template <int MODE>
__device__ __forceinline__ void gemm_body(const GemmArgs& g, int bx, int by, int b)
{
    extern __shared__ char smem[];
    const uint32_t sb = smem_u32(smem);
    const int tid = threadIdx.x, wid = tid >> 5, lane = tid & 31;
    const long m0 = (long)by * 128, n0 = (long)bx * 128;
    const int wm = (wid >> 2) * 64;
    const int wn = (wid & 3) * 32;

    const __half* Ah = g.Ah + (long)b * g.Abatch;
    const __half* Bh = g.Bh + (long)b * g.Bbatch;

    const int lrow = tid >> 3, lch = tid & 7;
    const uint32_t sw0 = swz64(lrow, lch);
    const long ga0 = (m0 + lrow) * g.lda + lch * 8;
    const long gb0 = (n0 + lrow) * g.ldb + lch * 8;
    const long astep = 32 * g.lda, bstep = 32 * g.ldb;

    const int NT = g.K >> 6;
    const int a_r = lane & 15, a_c = lane >> 4;
    const int b_r = (lane & 7) + ((lane >> 4) & 1) * 8, b_c = (lane >> 3) & 1;

    float acc[4][4][4];
#pragma unroll
    for (int i = 0; i < 4; i++)
#pragma unroll
        for (int j = 0; j < 4; j++)
#pragma unroll
            for (int k = 0; k < 4; k++) acc[i][j][k] = 0.0f;

    auto load_stage = [&](int s, int it) {
        const long k0 = (long)it << 6;
        const uint32_t base = sb + s * STG;
#pragma unroll
        for (int i = 0; i < 4; i++) {
            CP16(base + sw0 + i * 4096,         (const char*)(Ah + ga0 + i * astep + k0));
            CP16(base + 16384 + sw0 + i * 4096, (const char*)(Bh + gb0 + i * bstep + k0));
        }
        CP_COMMIT();
    };

    load_stage(0, 0);
    load_stage(1, 1);

    // warm L2 with the epilogue's gmem inputs while the mainloop runs
    if (MODE == 1) {
#pragma unroll
        for (int i = 0; i < 2; i++) {
            const int gid = tid + i * 256;           // 512 ids: 128 rows x 4 segs
            const int row = gid >> 2, seg = gid & 3;
            const long idx = (long)b * g.Cbatch + (m0 + row) * g.ldc + n0 + seg * 32;
            PREF_L2(g.align + idx);
            PREF_L2(g.mask + idx);
        }
    } else if (MODE == 3) {
#pragma unroll
        for (int i = 0; i < 2; i++) {
            const int gid = tid + i * 256;
            const int row = gid >> 2, seg = gid & 3;
            const long idx = (long)b * g.Cbatch + (m0 + row) * g.ldc + n0 + seg * 32;
            PREF_L2(g.Cf + idx);
        }
    }

    int cur = 0, nxt = 2;
    for (int it = 0; it < NT; ++it) {
        asm volatile("cp.async.wait_group 1;");
        __syncthreads();
        if (it + 2 < NT) {
            load_stage(nxt, it + 2);
            if (++nxt == NSTG) nxt = 0;
        } else CP_COMMIT();

        const uint32_t st = sb + cur * STG;
        if (++cur == NSTG) cur = 0;
#pragma unroll
        for (int ks = 0; ks < 4; ks++) {
            const int kc = ks * 2;
            uint32_t ah[4][4], bh[2][4];
#pragma unroll
            for (int mi = 0; mi < 4; mi++)
                LDSM4(ah[mi], st + swz64(wm + mi * 16 + a_r, kc + a_c));
#pragma unroll
            for (int nb = 0; nb < 2; nb++)
                LDSM4(bh[nb], st + 16384 + swz64(wn + nb * 16 + b_r, kc + b_c));
#pragma unroll
            for (int mi = 0; mi < 4; mi++)
#pragma unroll
                for (int ni = 0; ni < 4; ni++) {
                    const int nb = ni >> 1, sub = (ni & 1) * 2;
                    MMA_F16(acc[mi][ni], ah[mi], bh[nb][sub], bh[nb][sub + 1]);
                }
        }
    }
    __syncthreads();   // pipeline smem now reusable as staging

    // ---- stage acc tile to smem ----
    float* sf = (float*)smem;
#pragma unroll
    for (int mi = 0; mi < 4; mi++)
#pragma unroll
        for (int ni = 0; ni < 4; ni++) {
            const int row = wm + mi * 16 + (lane >> 2);
            const int col = wn + ni * 8 + (lane & 3) * 2;
            *(float2*)&sf[row * EPIT + col] =
                make_float2(acc[mi][ni][0], acc[mi][ni][1]);
            *(float2*)&sf[(row + 8) * EPIT + col] =
                make_float2(acc[mi][ni][2], acc[mi][ni][3]);
        }
    __syncthreads();

    // ---- thread-linear gmem phase: coalesced 16B transactions ----
    if (MODE == 0) {
        const float sc = g.scale;
#pragma unroll
        for (int i = 0; i < 8; i++) {
            const int gid = tid + i * 256;
            const int row = gid >> 4, c0 = (gid & 15) * 8;
            float4 va = *(float4*)&sf[row * EPIT + c0];
            float4 vb = *(float4*)&sf[row * EPIT + c0 + 4];
            float v[8] = {va.x, va.y, va.z, va.w, vb.x, vb.y, vb.z, vb.w};
            if (g.bias) {
                if (g.bias_rows) {
                    const float br = __ldg(&g.bias[m0 + row]);
#pragma unroll
                    for (int j = 0; j < 8; j++) v[j] += br;
                } else {
                    float4 b0 = *(const float4*)&g.bias[n0 + c0];
                    float4 b1 = *(const float4*)&g.bias[n0 + c0 + 4];
                    v[0] += b0.x; v[1] += b0.y; v[2] += b0.z; v[3] += b0.w;
                    v[4] += b1.x; v[5] += b1.y; v[6] += b1.z; v[7] += b1.w;
                }
            }
            uint4 u;
            __half2 h0 = {__float2half_rn(v[0] * sc), __float2half_rn(v[1] * sc)};
            __half2 h1 = {__float2half_rn(v[2] * sc), __float2half_rn(v[3] * sc)};
            __half2 h2 = {__float2half_rn(v[4] * sc), __float2half_rn(v[5] * sc)};
            __half2 h3 = {__float2half_rn(v[6] * sc), __float2half_rn(v[7] * sc)};
            u.x = *(uint32_t*)&h0; u.y = *(uint32_t*)&h1;
            u.z = *(uint32_t*)&h2; u.w = *(uint32_t*)&h3;
            const long idx = (long)b * g.Cbatch + (m0 + row) * g.ldc + n0 + c0;
            *(uint4*)(g.Chi + idx) = u;
        }
    } else if (MODE == 1) {
        const float sig = 1.0f / (1.0f + expf(-__ldg(g.alignw)));
#pragma unroll
        for (int i = 0; i < 16; i++) {
            const int gid = tid + i * 256;
            const int row = gid >> 5, c0 = (gid & 31) * 4;
            float4 v = *(float4*)&sf[row * EPIT + c0];
            const long idx = (long)b * g.Cbatch + (m0 + row) * g.ldc + n0 + c0;
            float4 av = *(const float4*)(g.align + idx);
            int4   mv = *(const int4*)(g.mask + idx);
            float o0 = fmaxf(v.x + sig * av.x, -FMAXV);
            float o1 = fmaxf(v.y + sig * av.y, -FMAXV);
            float o2 = fmaxf(v.z + sig * av.z, -FMAXV);
            float o3 = fmaxf(v.w + sig * av.w, -FMAXV);
            if (mv.x != 0) o0 = fmaxf(o0 - FMAXV, -FMAXV);
            if (mv.y != 0) o1 = fmaxf(o1 - FMAXV, -FMAXV);
            if (mv.z != 0) o2 = fmaxf(o2 - FMAXV, -FMAXV);
            if (mv.w != 0) o3 = fmaxf(o3 - FMAXV, -FMAXV);
            *(float4*)(g.Cf + idx) = make_float4(o0, o1, o2, o3);
        }
    } else if (MODE == 2) {
#pragma unroll
        for (int i = 0; i < 16; i++) {
            const int gid = tid + i * 256;
            const int row = gid >> 5, c0 = (gid & 31) * 4;
            float4 v = *(float4*)&sf[row * EPIT + c0];
            float4 b4 = *(const float4*)&g.bias[n0 + c0];
            const long idx = (long)b * g.Cbatch + (m0 + row) * g.ldc + n0 + c0;
            *(float4*)(g.Cf + idx) =
                make_float4(v.x + b4.x, v.y + b4.y, v.z + b4.z, v.w + b4.w);
        }
    } else {  // MODE 3: accumulate
#pragma unroll
        for (int i = 0; i < 16; i++) {
            const int gid = tid + i * 256;
            const int row = gid >> 5, c0 = (gid & 31) * 4;
            float4 v = *(float4*)&sf[row * EPIT + c0];
            const long idx = (long)b * g.Cbatch + (m0 + row) * g.ldc + n0 + c0;
            float4 o = *(float4*)(g.Cf + idx);
            *(float4*)(g.Cf + idx) =
                make_float4(v.x + o.x, v.y + o.y, v.z + o.z, v.w + o.w);
        }
    }
}

template <int MODE>
__global__ __launch_bounds__(256, 2) void mma_gemm(GemmArgs g)
{
    gemm_body<MODE>(g, blockIdx.x, blockIdx.y, blockIdx.z);
}

// merged projections (xk, yq)
struct Gemm2 { GemmArgs a[2]; long Mrows[2]; };
__global__ __launch_bounds__(256, 2) void mma_gemm_proj(Gemm2 p)
{
    const int z = blockIdx.z;
    if ((long)blockIdx.y * 128 >= p.Mrows[z]) return;
    gemm_body<0>(p.a[z], blockIdx.x, blockIdx.y, 0);
}

// mega: logits (1024) | xvT (512) | out1 (512) — all mutually independent
struct Gemm3 { GemmArgs lg, xv, o1; };
__global__ __launch_bounds__(256, 2) void mma_mega(Gemm3 p)
{
    const int id = blockIdx.x;
    if (id < 1024) {
        gemm_body<1>(p.lg, id & 15, (id >> 4) & 7, id >> 7);
    } else if (id < 1536) {
        const int t = id - 1024;
        gemm_body<0>(p.xv, t & 15, (t >> 4) & 3, t >> 6);
    } else {
        const int t = id - 1536;
        gemm_body<2>(p.o1, t & 7, t >> 3, 0);
    }
}

// ===================== launch ============================================
extern "C" void kernel_launch(void* const* d_in, const int* in_sizes, int n_in,
                              void* d_out, int out_size)
{
    const float* X         = (const float*)d_in[0];
    const float* Y         = (const float*)d_in[1];
    const float* alignment = (const float*)d_in[2];
    const int*   mask      = (const int*)d_in[3];
    const float* Xk_w      = (const float*)d_in[4];
    const float* Xk_b      = (const float*)d_in[5];
    const float* Xv_w      = (const float*)d_in[6];
    const float* Xv_b      = (const float*)d_in[7];
    const float* Yq_w      = (const float*)d_in[8];
    const float* Yq_b      = (const float*)d_in[9];
    const float* Yw_w      = (const float*)d_in[10];
    const float* Yw_b      = (const float*)d_in[11];
    const float* align_w   = (const float*)d_in[12];
    float* out = (float*)d_out;

    cudaFuncSetAttribute((const void*)mma_gemm<0>, cudaFuncAttributeMaxDynamicSharedMemorySize, SMEM_BYTES);
    cudaFuncSetAttribute((const void*)mma_gemm<3>, cudaFuncAttributeMaxDynamicSharedMemorySize, SMEM_BYTES);
    cudaFuncSetAttribute((const void*)mma_gemm_proj, cudaFuncAttributeMaxDynamicSharedMemorySize, SMEM_BYTES);
    cudaFuncSetAttribute((const void*)mma_mega, cudaFuncAttributeMaxDynamicSharedMemorySize, SMEM_BYTES);

#define SYM(p, s) do { void* _t; cudaGetSymbolAddress(&_t, s); p = (decltype(p))_t; } while (0)
    __half *Xhi, *Yhi, *Xkw_hi, *Xvw_hi, *Yqw_hi, *Yww_hi,
        *xk_hi, *yq_hi, *xvT_hi, *af_hi, *attn_hi;
    float* logits;
    SYM(Xhi, g_Xhi); SYM(Yhi, g_Yhi);
    SYM(Xkw_hi, g_Xkw_hi); SYM(Xvw_hi, g_Xvw_hi);
    SYM(Yqw_hi, g_Yqw_hi); SYM(Yww_hi, g_Yww_hi);
    SYM(xk_hi, g_xk_hi); SYM(yq_hi, g_yq_hi); SYM(xvT_hi, g_xvT_hi);
    SYM(af_hi, g_af_hi); SYM(attn_hi, g_attn_hi); SYM(logits, g_logits);

    // ---- fused split (1 launch, contiguous hi-only) ----
    SplitArgs sa;
    sa.src[0] = X;    sa.hi[0] = Xhi;    sa.n4[0] = (long)XLEN * BSZ * XD / 4;
    sa.src[1] = Y;    sa.hi[1] = Yhi;    sa.n4[1] = (long)YLEN * BSZ * YD / 4;
    sa.src[2] = Xk_w; sa.hi[2] = Xkw_hi; sa.n4[2] = (long)HD * XD / 4;
    sa.src[3] = Xv_w; sa.hi[3] = Xvw_hi; sa.n4[3] = (long)HD * XD / 4;
    sa.src[4] = Yq_w; sa.hi[4] = Yqw_hi; sa.n4[4] = (long)HD * YD / 4;
    sa.src[5] = Yw_w; sa.hi[5] = Yww_hi; sa.n4[5] = (long)YOUT * CATD / 4;
    long maxn4 = sa.n4[0];
    for (int i = 1; i < 6; i++) if (sa.n4[i] > maxn4) maxn4 = sa.n4[i];
    split_all<<<dim3((unsigned)((maxn4 + 255) / 256), 6), 256>>>(sa);

    // ---- merged projections: xk, yq ----
    Gemm2 p2 = {};
    {
        GemmArgs a = {};
        a.Ah = Xhi; a.lda = XD; a.Abatch = 0;
        a.Bh = Xkw_hi; a.ldb = XD; a.Bbatch = 0;
        a.K = XD; a.Chi = xk_hi; a.ldc = HD; a.Cbatch = 0;
        a.bias = Xk_b; a.bias_rows = 0; a.scale = 1.0f;
        p2.a[0] = a; p2.Mrows[0] = (long)XLEN * BSZ;

        a.Ah = Yhi; a.lda = YD;
        a.Bh = Yqw_hi; a.ldb = YD;
        a.Chi = yq_hi; a.bias = Yq_b; a.scale = INV_SQRT_HD;
        p2.a[1] = a; p2.Mrows[1] = (long)YLEN * BSZ;
    }
    mma_gemm_proj<<<dim3(HD / 128, XLEN * BSZ / 128, 2), 256, SMEM_BYTES>>>(p2);

    // ---- mega: logits + xvT + out1 (one 2048-block launch) ----
    Gemm3 p3 = {};
    {
        GemmArgs a = {};
        // logits: per batch M=1024(y) N=2048(x) K=512
        a.Ah = yq_hi; a.lda = BSZ * HD; a.Abatch = HD;
        a.Bh = xk_hi; a.ldb = BSZ * HD; a.Bbatch = HD;
        a.K = HD; a.Cf = logits; a.ldc = XLEN; a.Cbatch = (long)YLEN * XLEN;
        a.align = alignment; a.mask = mask; a.alignw = align_w; a.scale = 1.0f;
        p3.lg = a;

        // xvT[b,h,x] = Xv_w @ X[.,b,.]^T + Xv_b(row) : M=512(h) N=2048(x) K=1024
        a = {};
        a.Ah = Xvw_hi; a.lda = XD; a.Abatch = 0;
        a.Bh = Xhi; a.ldb = (long)BSZ * XD; a.Bbatch = XD;
        a.K = XD; a.Chi = xvT_hi; a.ldc = XLEN; a.Cbatch = (long)HD * XLEN;
        a.bias = Xv_b; a.bias_rows = 1; a.scale = 1.0f;
        p3.xv = a;

        // out1 = Y @ Yw[:, :YD]^T + bias : M=8192 N=1024 K=1024
        a = {};
        a.Ah = Yhi; a.lda = YD; a.Abatch = 0;
        a.Bh = Yww_hi; a.ldb = CATD; a.Bbatch = 0;
        a.K = YD; a.Cf = out; a.ldc = YOUT; a.Cbatch = 0;
        a.bias = Yw_b; a.bias_rows = 0; a.scale = 1.0f;
        p3.o1 = a;
    }
    mma_mega<<<2048, 256, SMEM_BYTES>>>(p3);

    // ---- softmax -> attn ----
    softmax_kernel<<<BSZ * YLEN, 256>>>();

    GemmArgs a = {};

    // ---- attn_feat = attn @ xvT^T -> af[(y,b),h] : per batch ----
    a.Ah = attn_hi; a.lda = XLEN; a.Abatch = (long)YLEN * XLEN;
    a.Bh = xvT_hi; a.ldb = XLEN; a.Bbatch = (long)HD * XLEN;
    a.K = XLEN; a.Chi = af_hi;
    a.ldc = (long)BSZ * HD; a.Cbatch = HD;
    a.bias = nullptr; a.bias_rows = 0; a.scale = 1.0f;
    mma_gemm<0><<<dim3(HD / 128, YLEN / 128, BSZ), 256, SMEM_BYTES>>>(a);

    // ---- out += af @ Yw[:, YD:]^T : M=8192 N=1024 K=512 (accumulate) ----
    a = {};
    a.Ah = af_hi; a.lda = HD; a.Abatch = 0;
    a.Bh = Yww_hi + YD; a.ldb = CATD; a.Bbatch = 0;
    a.K = HD; a.Cf = out; a.ldc = YOUT; a.Cbatch = 0;
    a.bias = nullptr; a.bias_rows = 0; a.scale = 1.0f;
    mma_gemm<3><<<dim3(YOUT / 128, YLEN * BSZ / 128, 1), 256, SMEM_BYTES>>>(a);
}

// round 12
// speedup vs baseline: 1.7337x; 1.0065x over previous
#include <cuda_runtime.h>
#include <cuda_fp16.h>
#include <math.h>
#include <stdint.h>

#define XLEN 2048
#define YLEN 1024
#define BSZ  8
#define XD   1024
#define YD   1024
#define HD   512
#define YOUT 1024
#define CATD (YD + HD)
#define FMAXV 3.402823466e38f
#define INV_SQRT_HD 0.04419417382415922f

// ===================== PTX helpers =====================
__device__ __forceinline__ uint32_t smem_u32(const void* p) {
    uint32_t a;
    asm("{ .reg .u64 t; cvta.to.shared.u64 t, %1; cvt.u32.u64 %0, t; }" : "=r"(a) : "l"(p));
    return a;
}
#define CP16(dst, src) \
    asm volatile("cp.async.cg.shared.global [%0], [%1], 16;" :: "r"(dst), "l"(src))
#define CP_COMMIT() asm volatile("cp.async.commit_group;")
#define PREF_L2(p) asm volatile("prefetch.global.L2 [%0];" :: "l"(p))

#define LDSM4(r, a) \
    asm volatile("ldmatrix.sync.aligned.m8n8.x4.shared.b16 {%0,%1,%2,%3}, [%4];" \
        : "=r"((r)[0]), "=r"((r)[1]), "=r"((r)[2]), "=r"((r)[3]) : "r"(a))

#define MMA_F16(d, a, b0v, b1v) \
    asm volatile("mma.sync.aligned.m16n8k16.row.col.f32.f16.f16.f32 " \
        "{%0,%1,%2,%3}, {%4,%5,%6,%7}, {%8,%9}, {%0,%1,%2,%3};" \
        : "+f"((d)[0]), "+f"((d)[1]), "+f"((d)[2]), "+f"((d)[3]) \
        : "r"((a)[0]), "r"((a)[1]), "r"((a)[2]), "r"((a)[3]), "r"(b0v), "r"(b1v))

// SMEM tile: 128 rows x 64 f16 (128B/row, 8 x 16B chunks), conflict-free swizzle.
__device__ __forceinline__ uint32_t swz64(int row, int ch) {
    return (uint32_t)(row * 128 + ((ch ^ (row & 7)) << 4));
}

// ===================== scratch (device globals) ==========================
#define AL __align__(16)
__device__ AL __half g_Xhi[XLEN * BSZ * XD];
__device__ AL __half g_Yhi[YLEN * BSZ * YD];
__device__ AL __half g_Xkw_hi[HD * XD];
__device__ AL __half g_Xvw_hi[HD * XD];
__device__ AL __half g_Yqw_hi[HD * YD];
__device__ AL __half g_Yww_hi[YOUT * CATD];
__device__ AL __half g_xk_hi[XLEN * BSZ * HD];
__device__ AL __half g_yq_hi[YLEN * BSZ * HD];
__device__ AL __half g_xvT_hi[BSZ * HD * XLEN];
__device__ AL __half g_af_hi[YLEN * BSZ * HD];
__device__ AL float  g_logits[BSZ * YLEN * XLEN];
__device__ AL __half g_attn_hi[BSZ * YLEN * XLEN];

// ===================== fused split: fp32 -> fp16 hi ======================
struct SplitArgs {
    const float* src[6];
    __half* hi[6];
    long n4[6];
};

__global__ __launch_bounds__(256) void split_all(SplitArgs s)
{
    const int e = blockIdx.y;
    long i4 = (long)blockIdx.x * 256 + threadIdx.x;
    if (i4 >= s.n4[e]) return;
    long base = i4 * 4;
    float4 v = *(const float4*)(s.src[e] + base);
    __half2 hp0 = {__float2half_rn(v.x), __float2half_rn(v.y)};
    __half2 hp1 = {__float2half_rn(v.z), __float2half_rn(v.w)};
    *(uint2*)(s.hi[e] + base) = make_uint2(*(uint32_t*)&hp0, *(uint32_t*)&hp1);
}

// ===================== softmax: fp32 logits -> fp16 attn =================
__global__ __launch_bounds__(256) void softmax_kernel()
{
    const long row = blockIdx.x;
    const float* p = g_logits + row * XLEN;
    __half* ah = g_attn_hi + row * XLEN;
    const int tid = threadIdx.x;

    float v[8];
    float mx = -FMAXV;
#pragma unroll
    for (int i = 0; i < 8; i++) { v[i] = p[tid + (i << 8)]; mx = fmaxf(mx, v[i]); }

    __shared__ float sred[8];
#pragma unroll
    for (int o = 16; o > 0; o >>= 1) mx = fmaxf(mx, __shfl_xor_sync(0xffffffff, mx, o));
    if ((tid & 31) == 0) sred[tid >> 5] = mx;
    __syncthreads();
    mx = sred[0];
#pragma unroll
    for (int w = 1; w < 8; w++) mx = fmaxf(mx, sred[w]);
    __syncthreads();

    float s = 0.0f;
#pragma unroll
    for (int i = 0; i < 8; i++) { v[i] = expf(v[i] - mx); s += v[i]; }
#pragma unroll
    for (int o = 16; o > 0; o >>= 1) s += __shfl_xor_sync(0xffffffff, s, o);
    if ((tid & 31) == 0) sred[tid >> 5] = s;
    __syncthreads();
    s = 0.0f;
#pragma unroll
    for (int w = 0; w < 8; w++) s += sred[w];

    const float inv = 1.0f / s;
#pragma unroll
    for (int i = 0; i < 8; i++)
        ah[tid + (i << 8)] = __float2half_rn(v[i] * inv);
}

// ===================== fp16 GEMM core ====================================
// C[M,N] = Ah[M,K] @ Bh[N,K]^T
// Block 128x128, BK=64, 8 warps (2x4), warp tile 64x32, 3-stage cp.async,
// 2 CTAs/SM. Smem-staged coalesced epilogues.
// MODE 0: fp16 out (+bias col/row, scale).  MODE 1: logits epilogue -> fp32.
// MODE 2: +bias -> fp32.  MODE 3: accumulate into fp32 C (no bias).
struct GemmArgs {
    const __half *Ah, *Bh;
    long lda, ldb, Abatch, Bbatch;
    int K;
    float* Cf;
    __half *Chi;
    long ldc, Cbatch;
    const float* bias;
    int bias_rows;
    float scale;
    const float* align;
    const int*   mask;
    const float* alignw;
};

#define STG   32768            // Ah 16K | Bh 16K
#define NSTG  3
#define EPIT  136
#define SMEM_BYTES (NSTG * STG)

template <int MODE>
__device__ __forceinline__ void gemm_body(const GemmArgs& g, int bx, int by, int b)
{
    extern __shared__ char smem[];
    const uint32_t sb = smem_u32(smem);
    const int tid = threadIdx.x, wid = tid >> 5, lane = tid & 31;
    const long m0 = (long)by * 128, n0 = (long)bx * 128;
    const int wm = (wid >> 2) * 64;
    const int wn = (wid & 3) * 32;

    const __half* Ah = g.Ah + (long)b * g.Abatch;
    const __half* Bh = g.Bh + (long)b * g.Bbatch;

    const int lrow = tid >> 3, lch = tid & 7;
    const uint32_t sw0 = swz64(lrow, lch);
    const long ga0 = (m0 + lrow) * g.lda + lch * 8;
    const long gb0 = (n0 + lrow) * g.ldb + lch * 8;
    const long astep = 32 * g.lda, bstep = 32 * g.ldb;

    const int NT = g.K >> 6;
    const int a_r = lane & 15, a_c = lane >> 4;
    const int b_r = (lane & 7) + ((lane >> 4) & 1) * 8, b_c = (lane >> 3) & 1;

    float acc[4][4][4];
#pragma unroll
    for (int i = 0; i < 4; i++)
#pragma unroll
        for (int j = 0; j < 4; j++)
#pragma unroll
            for (int k = 0; k < 4; k++) acc[i][j][k] = 0.0f;

    auto load_stage = [&](int s, int it) {
        const long k0 = (long)it << 6;
        const uint32_t base = sb + s * STG;
#pragma unroll
        for (int i = 0; i < 4; i++) {
            CP16(base + sw0 + i * 4096,         (const char*)(Ah + ga0 + i * astep + k0));
            CP16(base + 16384 + sw0 + i * 4096, (const char*)(Bh + gb0 + i * bstep + k0));
        }
        CP_COMMIT();
    };

    load_stage(0, 0);
    load_stage(1, 1);

    // warm L2 with the epilogue's gmem inputs while the mainloop runs
    if (MODE == 1) {
#pragma unroll
        for (int i = 0; i < 2; i++) {
            const int gid = tid + i * 256;           // 512 ids: 128 rows x 4 segs
            const int row = gid >> 2, seg = gid & 3;
            const long idx = (long)b * g.Cbatch + (m0 + row) * g.ldc + n0 + seg * 32;
            PREF_L2(g.align + idx);
            PREF_L2(g.mask + idx);
        }
    } else if (MODE == 3) {
#pragma unroll
        for (int i = 0; i < 2; i++) {
            const int gid = tid + i * 256;
            const int row = gid >> 2, seg = gid & 3;
            const long idx = (long)b * g.Cbatch + (m0 + row) * g.ldc + n0 + seg * 32;
            PREF_L2(g.Cf + idx);
        }
    }

    int cur = 0, nxt = 2;
    for (int it = 0; it < NT; ++it) {
        asm volatile("cp.async.wait_group 1;");
        __syncthreads();
        if (it + 2 < NT) {
            load_stage(nxt, it + 2);
            if (++nxt == NSTG) nxt = 0;
        } else CP_COMMIT();

        const uint32_t st = sb + cur * STG;
        if (++cur == NSTG) cur = 0;
#pragma unroll
        for (int ks = 0; ks < 4; ks++) {
            const int kc = ks * 2;
            uint32_t ah[4][4], bh[2][4];
#pragma unroll
            for (int mi = 0; mi < 4; mi++)
                LDSM4(ah[mi], st + swz64(wm + mi * 16 + a_r, kc + a_c));
#pragma unroll
            for (int nb = 0; nb < 2; nb++)
                LDSM4(bh[nb], st + 16384 + swz64(wn + nb * 16 + b_r, kc + b_c));
#pragma unroll
            for (int mi = 0; mi < 4; mi++)
#pragma unroll
                for (int ni = 0; ni < 4; ni++) {
                    const int nb = ni >> 1, sub = (ni & 1) * 2;
                    MMA_F16(acc[mi][ni], ah[mi], bh[nb][sub], bh[nb][sub + 1]);
                }
        }
    }
    __syncthreads();   // pipeline smem now reusable as staging

    // ---- stage acc tile to smem ----
    float* sf = (float*)smem;
#pragma unroll
    for (int mi = 0; mi < 4; mi++)
#pragma unroll
        for (int ni = 0; ni < 4; ni++) {
            const int row = wm + mi * 16 + (lane >> 2);
            const int col = wn + ni * 8 + (lane & 3) * 2;
            *(float2*)&sf[row * EPIT + col] =
                make_float2(acc[mi][ni][0], acc[mi][ni][1]);
            *(float2*)&sf[(row + 8) * EPIT + col] =
                make_float2(acc[mi][ni][2], acc[mi][ni][3]);
        }
    __syncthreads();

    // ---- thread-linear gmem phase: coalesced 16B transactions ----
    if (MODE == 0) {
        const float sc = g.scale;
#pragma unroll
        for (int i = 0; i < 8; i++) {
            const int gid = tid + i * 256;
            const int row = gid >> 4, c0 = (gid & 15) * 8;
            float4 va = *(float4*)&sf[row * EPIT + c0];
            float4 vb = *(float4*)&sf[row * EPIT + c0 + 4];
            float v[8] = {va.x, va.y, va.z, va.w, vb.x, vb.y, vb.z, vb.w};
            if (g.bias) {
                if (g.bias_rows) {
                    const float br = __ldg(&g.bias[m0 + row]);
#pragma unroll
                    for (int j = 0; j < 8; j++) v[j] += br;
                } else {
                    float4 b0 = *(const float4*)&g.bias[n0 + c0];
                    float4 b1 = *(const float4*)&g.bias[n0 + c0 + 4];
                    v[0] += b0.x; v[1] += b0.y; v[2] += b0.z; v[3] += b0.w;
                    v[4] += b1.x; v[5] += b1.y; v[6] += b1.z; v[7] += b1.w;
                }
            }
            uint4 u;
            __half2 h0 = {__float2half_rn(v[0] * sc), __float2half_rn(v[1] * sc)};
            __half2 h1 = {__float2half_rn(v[2] * sc), __float2half_rn(v[3] * sc)};
            __half2 h2 = {__float2half_rn(v[4] * sc), __float2half_rn(v[5] * sc)};
            __half2 h3 = {__float2half_rn(v[6] * sc), __float2half_rn(v[7] * sc)};
            u.x = *(uint32_t*)&h0; u.y = *(uint32_t*)&h1;
            u.z = *(uint32_t*)&h2; u.w = *(uint32_t*)&h3;
            const long idx = (long)b * g.Cbatch + (m0 + row) * g.ldc + n0 + c0;
            *(uint4*)(g.Chi + idx) = u;
        }
    } else if (MODE == 1) {
        const float sig = 1.0f / (1.0f + expf(-__ldg(g.alignw)));
#pragma unroll
        for (int i = 0; i < 16; i++) {
            const int gid = tid + i * 256;
            const int row = gid >> 5, c0 = (gid & 31) * 4;
            float4 v = *(float4*)&sf[row * EPIT + c0];
            const long idx = (long)b * g.Cbatch + (m0 + row) * g.ldc + n0 + c0;
            float4 av = *(const float4*)(g.align + idx);
            int4   mv = *(const int4*)(g.mask + idx);
            float o0 = fmaxf(v.x + sig * av.x, -FMAXV);
            float o1 = fmaxf(v.y + sig * av.y, -FMAXV);
            float o2 = fmaxf(v.z + sig * av.z, -FMAXV);
            float o3 = fmaxf(v.w + sig * av.w, -FMAXV);
            if (mv.x != 0) o0 = fmaxf(o0 - FMAXV, -FMAXV);
            if (mv.y != 0) o1 = fmaxf(o1 - FMAXV, -FMAXV);
            if (mv.z != 0) o2 = fmaxf(o2 - FMAXV, -FMAXV);
            if (mv.w != 0) o3 = fmaxf(o3 - FMAXV, -FMAXV);
            *(float4*)(g.Cf + idx) = make_float4(o0, o1, o2, o3);
        }
    } else if (MODE == 2) {
#pragma unroll
        for (int i = 0; i < 16; i++) {
            const int gid = tid + i * 256;
            const int row = gid >> 5, c0 = (gid & 31) * 4;
            float4 v = *(float4*)&sf[row * EPIT + c0];
            float4 b4 = *(const float4*)&g.bias[n0 + c0];
            const long idx = (long)b * g.Cbatch + (m0 + row) * g.ldc + n0 + c0;
            *(float4*)(g.Cf + idx) =
                make_float4(v.x + b4.x, v.y + b4.y, v.z + b4.z, v.w + b4.w);
        }
    } else {  // MODE 3: accumulate
#pragma unroll
        for (int i = 0; i < 16; i++) {
            const int gid = tid + i * 256;
            const int row = gid >> 5, c0 = (gid & 31) * 4;
            float4 v = *(float4*)&sf[row * EPIT + c0];
            const long idx = (long)b * g.Cbatch + (m0 + row) * g.ldc + n0 + c0;
            float4 o = *(float4*)(g.Cf + idx);
            *(float4*)(g.Cf + idx) =
                make_float4(v.x + o.x, v.y + o.y, v.z + o.z, v.w + o.w);
        }
    }
}

template <int MODE>
__global__ __launch_bounds__(256, 2) void mma_gemm(GemmArgs g)
{
    gemm_body<MODE>(g, blockIdx.x, blockIdx.y, blockIdx.z);
}

// merged projections (xk, yq), striped 2:1 so waves mix both
struct Gemm2 { GemmArgs a[2]; };
__global__ __launch_bounds__(256, 2) void mma_gemm_proj(Gemm2 p)
{
    const int id = blockIdx.x;         // 768 = 256 groups x {xk, xk, yq}
    const int grp = id / 3, r = id - grp * 3;
    if (r < 2) {
        const int t = grp * 2 + r;     // 0..511 : xk  (4 nblk x 128 mblk)
        gemm_body<0>(p.a[0], t & 3, t >> 2, 0);
    } else {
        const int t = grp;             // 0..255 : yq  (4 nblk x 64 mblk)
        gemm_body<0>(p.a[1], t & 3, t >> 2, 0);
    }
}

// mega: logits(1024) | xvT(512) | out1(512), striped {lg,lg,xv,o1} per 4 ids
struct Gemm3 { GemmArgs lg, xv, o1; };
__global__ __launch_bounds__(256, 2) void mma_mega(Gemm3 p)
{
    const int id = blockIdx.x;
    const int grp = id >> 2, r = id & 3;
    if (r < 2) {
        const int t = grp * 2 + r;     // 0..1023 : logits (16 x 8 x 8)
        gemm_body<1>(p.lg, t & 15, (t >> 4) & 7, t >> 7);
    } else if (r == 2) {
        const int t = grp;             // 0..511 : xvT (16 x 4 x 8)
        gemm_body<0>(p.xv, t & 15, (t >> 4) & 3, t >> 6);
    } else {
        const int t = grp;             // 0..511 : out1 (8 x 64)
        gemm_body<2>(p.o1, t & 7, t >> 3, 0);
    }
}

// ===================== launch ============================================
extern "C" void kernel_launch(void* const* d_in, const int* in_sizes, int n_in,
                              void* d_out, int out_size)
{
    const float* X         = (const float*)d_in[0];
    const float* Y         = (const float*)d_in[1];
    const float* alignment = (const float*)d_in[2];
    const int*   mask      = (const int*)d_in[3];
    const float* Xk_w      = (const float*)d_in[4];
    const float* Xk_b      = (const float*)d_in[5];
    const float* Xv_w      = (const float*)d_in[6];
    const float* Xv_b      = (const float*)d_in[7];
    const float* Yq_w      = (const float*)d_in[8];
    const float* Yq_b      = (const float*)d_in[9];
    const float* Yw_w      = (const float*)d_in[10];
    const float* Yw_b      = (const float*)d_in[11];
    const float* align_w   = (const float*)d_in[12];
    float* out = (float*)d_out;

    cudaFuncSetAttribute((const void*)mma_gemm<0>, cudaFuncAttributeMaxDynamicSharedMemorySize, SMEM_BYTES);
    cudaFuncSetAttribute((const void*)mma_gemm<3>, cudaFuncAttributeMaxDynamicSharedMemorySize, SMEM_BYTES);
    cudaFuncSetAttribute((const void*)mma_gemm_proj, cudaFuncAttributeMaxDynamicSharedMemorySize, SMEM_BYTES);
    cudaFuncSetAttribute((const void*)mma_mega, cudaFuncAttributeMaxDynamicSharedMemorySize, SMEM_BYTES);

#define SYM(p, s) do { void* _t; cudaGetSymbolAddress(&_t, s); p = (decltype(p))_t; } while (0)
    __half *Xhi, *Yhi, *Xkw_hi, *Xvw_hi, *Yqw_hi, *Yww_hi,
        *xk_hi, *yq_hi, *xvT_hi, *af_hi, *attn_hi;
    float* logits;
    SYM(Xhi, g_Xhi); SYM(Yhi, g_Yhi);
    SYM(Xkw_hi, g_Xkw_hi); SYM(Xvw_hi, g_Xvw_hi);
    SYM(Yqw_hi, g_Yqw_hi); SYM(Yww_hi, g_Yww_hi);
    SYM(xk_hi, g_xk_hi); SYM(yq_hi, g_yq_hi); SYM(xvT_hi, g_xvT_hi);
    SYM(af_hi, g_af_hi); SYM(attn_hi, g_attn_hi); SYM(logits, g_logits);

    // ---- fused split (1 launch, contiguous hi-only) ----
    SplitArgs sa;
    sa.src[0] = X;    sa.hi[0] = Xhi;    sa.n4[0] = (long)XLEN * BSZ * XD / 4;
    sa.src[1] = Y;    sa.hi[1] = Yhi;    sa.n4[1] = (long)YLEN * BSZ * YD / 4;
    sa.src[2] = Xk_w; sa.hi[2] = Xkw_hi; sa.n4[2] = (long)HD * XD / 4;
    sa.src[3] = Xv_w; sa.hi[3] = Xvw_hi; sa.n4[3] = (long)HD * XD / 4;
    sa.src[4] = Yq_w; sa.hi[4] = Yqw_hi; sa.n4[4] = (long)HD * YD / 4;
    sa.src[5] = Yw_w; sa.hi[5] = Yww_hi; sa.n4[5] = (long)YOUT * CATD / 4;
    long maxn4 = sa.n4[0];
    for (int i = 1; i < 6; i++) if (sa.n4[i] > maxn4) maxn4 = sa.n4[i];
    split_all<<<dim3((unsigned)((maxn4 + 255) / 256), 6), 256>>>(sa);

    // ---- merged projections: xk, yq (striped) ----
    Gemm2 p2 = {};
    {
        GemmArgs a = {};
        a.Ah = Xhi; a.lda = XD; a.Abatch = 0;
        a.Bh = Xkw_hi; a.ldb = XD; a.Bbatch = 0;
        a.K = XD; a.Chi = xk_hi; a.ldc = HD; a.Cbatch = 0;
        a.bias = Xk_b; a.bias_rows = 0; a.scale = 1.0f;
        p2.a[0] = a;

        a.Ah = Yhi; a.lda = YD;
        a.Bh = Yqw_hi; a.ldb = YD;
        a.Chi = yq_hi; a.bias = Yq_b; a.scale = INV_SQRT_HD;
        p2.a[1] = a;
    }
    mma_gemm_proj<<<768, 256, SMEM_BYTES>>>(p2);

    // ---- mega: logits + xvT + out1 (striped 2048-block launch) ----
    Gemm3 p3 = {};
    {
        GemmArgs a = {};
        // logits: per batch M=1024(y) N=2048(x) K=512
        a.Ah = yq_hi; a.lda = BSZ * HD; a.Abatch = HD;
        a.Bh = xk_hi; a.ldb = BSZ * HD; a.Bbatch = HD;
        a.K = HD; a.Cf = logits; a.ldc = XLEN; a.Cbatch = (long)YLEN * XLEN;
        a.align = alignment; a.mask = mask; a.alignw = align_w; a.scale = 1.0f;
        p3.lg = a;

        // xvT[b,h,x] = Xv_w @ X[.,b,.]^T + Xv_b(row) : M=512(h) N=2048(x) K=1024
        a = {};
        a.Ah = Xvw_hi; a.lda = XD; a.Abatch = 0;
        a.Bh = Xhi; a.ldb = (long)BSZ * XD; a.Bbatch = XD;
        a.K = XD; a.Chi = xvT_hi; a.ldc = XLEN; a.Cbatch = (long)HD * XLEN;
        a.bias = Xv_b; a.bias_rows = 1; a.scale = 1.0f;
        p3.xv = a;

        // out1 = Y @ Yw[:, :YD]^T + bias : M=8192 N=1024 K=1024
        a = {};
        a.Ah = Yhi; a.lda = YD; a.Abatch = 0;
        a.Bh = Yww_hi; a.ldb = CATD; a.Bbatch = 0;
        a.K = YD; a.Cf = out; a.ldc = YOUT; a.Cbatch = 0;
        a.bias = Yw_b; a.bias_rows = 0; a.scale = 1.0f;
        p3.o1 = a;
    }
    mma_mega<<<2048, 256, SMEM_BYTES>>>(p3);

    // ---- softmax -> attn ----
    softmax_kernel<<<BSZ * YLEN, 256>>>();

    GemmArgs a = {};

    // ---- attn_feat = attn @ xvT^T -> af[(y,b),h] : per batch ----
    a.Ah = attn_hi; a.lda = XLEN; a.Abatch = (long)YLEN * XLEN;
    a.Bh = xvT_hi; a.ldb = XLEN; a.Bbatch = (long)HD * XLEN;
    a.K = XLEN; a.Chi = af_hi;
    a.ldc = (long)BSZ * HD; a.Cbatch = HD;
    a.bias = nullptr; a.bias_rows = 0; a.scale = 1.0f;
    mma_gemm<0><<<dim3(HD / 128, YLEN / 128, BSZ), 256, SMEM_BYTES>>>(a);

    // ---- out += af @ Yw[:, YD:]^T : M=8192 N=1024 K=512 (accumulate) ----
    a = {};
    a.Ah = af_hi; a.lda = HD; a.Abatch = 0;
    a.Bh = Yww_hi + YD; a.ldb = CATD; a.Bbatch = 0;
    a.K = HD; a.Cf = out; a.ldc = YOUT; a.Cbatch = 0;
    a.bias = nullptr; a.bias_rows = 0; a.scale = 1.0f;
    mma_gemm<3><<<dim3(YOUT / 128, YLEN * BSZ / 128, 1), 256, SMEM_BYTES>>>(a);
}